// round 5
// baseline (speedup 1.0000x reference)
#include <cuda_runtime.h>
#include <cstdint>
#include <cstddef>

#define NN 2048
#define EPS 1e-5f

// ---------------- scratch (device globals; allocation-free rule) ----------------
__device__ float g_Wcat[768 * 576];          // packed [w1 | watt | wif]
__device__ float g_bcat[576];                // packed [b1 | batt | bif]
__device__ float g_P[2 * NN * 576];          // Pi (part 0), Pj (part 1)

__device__ __forceinline__ float warp_sum(float v) {
#pragma unroll
    for (int o = 16; o; o >>= 1) v += __shfl_xor_sync(0xffffffffu, v, o);
    return v;
}
__device__ __forceinline__ float warp_max(float v) {
#pragma unroll
    for (int o = 16; o; o >>= 1) v = fmaxf(v, __shfl_xor_sync(0xffffffffu, v, o));
    return v;
}

// swizzled index into ash: k-major, 64 floats/row, 4-float blocks XOR-swizzled by k
__device__ __forceinline__ int swz(int k, int row) {
    return (k << 6) + ((row & 60) ^ ((k << 2) & 60)) + (row & 3);
}

// scalar 4x4 micro (p_kernel only)
__device__ __forceinline__ void micro_fma32(const float* __restrict__ ap,
                                            const float* __restrict__ bp,
                                            float acc[4][4]) {
#pragma unroll 8
    for (int k = 0; k < 32; k++) {
        const float* apk = ap + k * 65;
        const float* bpk = bp + k * 65;
        float a0 = apk[0], a1 = apk[1], a2 = apk[2], a3 = apk[3];
        float b0 = bpk[0], b1 = bpk[1], b2 = bpk[2], b3 = bpk[3];
        acc[0][0] += a0 * b0; acc[0][1] += a0 * b1; acc[0][2] += a0 * b2; acc[0][3] += a0 * b3;
        acc[1][0] += a1 * b0; acc[1][1] += a1 * b1; acc[1][2] += a1 * b2; acc[1][3] += a1 * b3;
        acc[2][0] += a2 * b0; acc[2][1] += a2 * b1; acc[2][2] += a2 * b2; acc[2][3] += a2 * b3;
        acc[3][0] += a3 * b0; acc[3][1] += a3 * b1; acc[3][2] += a3 * b2; acc[3][3] += a3 * b3;
    }
}

// packed f32x2 micro: 32 k-steps, 4x4 tile as 8 fma.rn.f32x2 per k.
// abase: shared byte addr of ash + (kbase<<8)   (kbase multiple of 32)
// bbase: shared byte addr of weight panel (+ tx*16)
// ty16 : byte offset of this thread's 4-row block within a 64-row group
__device__ __forceinline__ void micro32x2(unsigned abase, unsigned bbase, int ty16,
                                          unsigned long long acc[4][2]) {
#pragma unroll
    for (int k = 0; k < 32; k++) {
        unsigned aaddr = abase + (unsigned)(k << 8) + (unsigned)(ty16 ^ ((k << 4) & 240));
        unsigned long long a01, a23;
        asm("ld.shared.v2.b64 {%0,%1}, [%2];" : "=l"(a01), "=l"(a23) : "r"(aaddr));
        float b0, b1, b2, b3;
        asm("ld.shared.v4.b32 {%0,%1,%2,%3}, [%4];"
            : "=f"(b0), "=f"(b1), "=f"(b2), "=f"(b3)
            : "r"(bbase + (unsigned)(k * 272)));
        unsigned long long B0, B1, B2, B3;
        asm("mov.b64 %0, {%1,%2};" : "=l"(B0) : "f"(b0), "f"(b0));
        asm("mov.b64 %0, {%1,%2};" : "=l"(B1) : "f"(b1), "f"(b1));
        asm("mov.b64 %0, {%1,%2};" : "=l"(B2) : "f"(b2), "f"(b2));
        asm("mov.b64 %0, {%1,%2};" : "=l"(B3) : "f"(b3), "f"(b3));
        asm("fma.rn.f32x2 %0, %1, %2, %0;" : "+l"(acc[0][0]) : "l"(a01), "l"(B0));
        asm("fma.rn.f32x2 %0, %1, %2, %0;" : "+l"(acc[0][1]) : "l"(a23), "l"(B0));
        asm("fma.rn.f32x2 %0, %1, %2, %0;" : "+l"(acc[1][0]) : "l"(a01), "l"(B1));
        asm("fma.rn.f32x2 %0, %1, %2, %0;" : "+l"(acc[1][1]) : "l"(a23), "l"(B1));
        asm("fma.rn.f32x2 %0, %1, %2, %0;" : "+l"(acc[2][0]) : "l"(a01), "l"(B2));
        asm("fma.rn.f32x2 %0, %1, %2, %0;" : "+l"(acc[2][1]) : "l"(a23), "l"(B2));
        asm("fma.rn.f32x2 %0, %1, %2, %0;" : "+l"(acc[3][0]) : "l"(a01), "l"(B3));
        asm("fma.rn.f32x2 %0, %1, %2, %0;" : "+l"(acc[3][1]) : "l"(a23), "l"(B3));
    }
}

// ---------------- K0: pack weights ----------------
__global__ void pack_kernel(const float* __restrict__ w1, const float* __restrict__ watt,
                            const float* __restrict__ wif, const float* __restrict__ b1,
                            const float* __restrict__ batt, const float* __restrict__ bif) {
    int idx = blockIdx.x * blockDim.x + threadIdx.x;
    if (idx < 768 * 576) {
        int r = idx / 576, c = idx - r * 576;
        float v = (c < 256) ? w1[r * 256 + c]
                 : (c < 320) ? watt[r * 64 + (c - 256)]
                             : wif[r * 256 + (c - 320)];
        g_Wcat[idx] = v;
    }
    if (idx < 576) {
        g_bcat[idx] = (idx < 256) ? b1[idx] : (idx < 320) ? batt[idx - 256] : bif[idx - 320];
    }
}

// ---------------- K1: P = x @ Wcat(part) ----------------
__global__ void __launch_bounds__(256) p_kernel(const float* __restrict__ x) {
    extern __shared__ float sm[];
    float* xs = sm;               // [256][65] transposed x tile
    float* wsh = xs + 256 * 65;   // [32][65]

    int nb = blockIdx.x, part = blockIdx.y;
    int t = threadIdx.x, ty = t >> 4, tx = t & 15;

    {
        int row = t >> 2, k0 = (t & 3) * 64;
        const float* src = x + (size_t)(nb * 64 + row) * 256 + k0;
#pragma unroll
        for (int k = 0; k < 64; k += 4) {
            float4 v = *(const float4*)(src + k);
            xs[(k0 + k) * 65 + row] = v.x; xs[(k0 + k + 1) * 65 + row] = v.y;
            xs[(k0 + k + 2) * 65 + row] = v.z; xs[(k0 + k + 3) * 65 + row] = v.w;
        }
    }
    __syncthreads();

    for (int cc = 0; cc < 9; cc++) {
        float acc[4][4] = {};
        for (int kp = 0; kp < 8; kp++) {
            {
                int k = t >> 3, cb = (t & 7) * 8;
                const float* src = g_Wcat + (size_t)(part * 256 + kp * 32 + k) * 576 + cc * 64 + cb;
                float4 v0 = *(const float4*)src, v1 = *(const float4*)(src + 4);
                float* d = wsh + k * 65 + cb;
                d[0] = v0.x; d[1] = v0.y; d[2] = v0.z; d[3] = v0.w;
                d[4] = v1.x; d[5] = v1.y; d[6] = v1.z; d[7] = v1.w;
            }
            __syncthreads();
            micro_fma32(xs + kp * 32 * 65 + ty * 4, wsh + tx * 4, acc);
            __syncthreads();
        }
#pragma unroll
        for (int ri = 0; ri < 4; ri++) {
            float4 v = make_float4(acc[ri][0], acc[ri][1], acc[ri][2], acc[ri][3]);
            *(float4*)(g_P + (size_t)part * NN * 576 +
                       (size_t)(nb * 64 + ty * 4 + ri) * 576 + cc * 64 + tx * 4) = v;
        }
    }
}

// ---------------- K2: fully fused per-n kernel ----------------
__global__ void __launch_bounds__(256) big_kernel(
    const float* __restrict__ IF, const int* __restrict__ ai, const int* __restrict__ aj,
    const float* __restrict__ g1, const float* __restrict__ be1,
    const float* __restrict__ gatt, const float* __restrict__ beatt,
    const float* __restrict__ gif, const float* __restrict__ beif,
    const float* __restrict__ w2, const float* __restrict__ b2,
    const float* __restrict__ g2, const float* __restrict__ be2,
    const float* __restrict__ wpre, const float* __restrict__ bpre,
    const int* __restrict__ mask,
    const float* __restrict__ wg, const float* __restrict__ bg,
    const float* __restrict__ gg, const float* __restrict__ beg,
    float* __restrict__ out) {
    extern __shared__ float sm[];
    float* tbuf = sm;                          // [64][576]
    float* ash  = sm + 36864;                  // [256][64] swizzled: IF^T, then h1^T
    float* wsh  = sm + 36864 + 16384;          // 2 x [32][68] weight panels
    int*   idxs = (int*)(sm + 36864 + 16384 + 4352);  // 128 ints
    // aliases in dead tbuf regions (cols 0..255 of rows 0..3 are free after phase 2)
    float* wsm  = tbuf;            // [4][64] softmax weights
    float* slog = tbuf + 576;      // [64][4] logits
    float* aggs = tbuf + 1152;     // [256]
    float* red  = tbuf + 1728;     // [16]

    const int n = blockIdx.x, t = threadIdx.x;
    const int lane = t & 31, wid = t >> 5;
    const int ty4 = (t >> 4) << 2, tx4 = (t & 15) << 2;
    const int ty16 = ty4 << 2;
    const unsigned tx16 = (unsigned)(tx4 << 2);
    const int wk = t >> 3, wc = (t & 7) * 8;
    const float NEG = __int_as_float(0xff800000);
    const unsigned asho = (unsigned)__cvta_generic_to_shared(ash);
    const unsigned wsho = (unsigned)__cvta_generic_to_shared(wsh);

    if (t < 64) { idxs[t] = ai[n * 64 + t]; idxs[64 + t] = aj[n * 64 + t]; }

    // load IF tile transposed + swizzled into ash
    {
        int row = t >> 2, k0 = (t & 3) * 64;
        const float* src = IF + (size_t)(n * 64 + row) * 256 + k0;
#pragma unroll 4
        for (int k = 0; k < 64; k += 4) {
            float4 v = *(const float4*)(src + k);
            ash[swz(k0 + k, row)]     = v.x;
            ash[swz(k0 + k + 1, row)] = v.y;
            ash[swz(k0 + k + 2, row)] = v.z;
            ash[swz(k0 + k + 3, row)] = v.w;
        }
    }

    // -------- Phase 1: t = IF @ Wf + Pi[i] + Pj[j] + bcat  (9 x 64-col tiles) --------
#pragma unroll 1
    for (int cc = 0; cc < 9; cc++) {
        const float* wsrc = g_Wcat + (size_t)512 * 576 + cc * 64;
        float4 r0 = *(const float4*)(wsrc + wk * 576 + wc);
        float4 r1 = *(const float4*)(wsrc + wk * 576 + wc + 4);
        *(float4*)(wsh + wk * 68 + wc) = r0;
        *(float4*)(wsh + wk * 68 + wc + 4) = r1;
        __syncthreads();
        unsigned long long acc[4][2] = {{0ull,0ull},{0ull,0ull},{0ull,0ull},{0ull,0ull}};
#pragma unroll 1
        for (int kp = 0; kp < 8; kp++) {
            if (kp < 7) {
                const float* s = wsrc + (size_t)(kp + 1) * 32 * 576 + wk * 576 + wc;
                r0 = *(const float4*)s; r1 = *(const float4*)(s + 4);
            }
            micro32x2(asho + (unsigned)((kp * 32) << 8),
                      wsho + (unsigned)((kp & 1) * 8704) + tx16, ty16, acc);
            if (kp < 7) {
                float* d = wsh + ((kp + 1) & 1) * 2176 + wk * 68 + wc;
                *(float4*)d = r0; *(float4*)(d + 4) = r1;
                __syncthreads();
            }
        }
        int c0 = cc * 64 + tx4;
        float4 bb = *(const float4*)(g_bcat + c0);
        float vals[4][4];
#pragma unroll
        for (int c = 0; c < 4; c++) {
            float lo, hi;
            asm("mov.b64 {%0,%1}, %2;" : "=f"(lo), "=f"(hi) : "l"(acc[c][0]));
            vals[0][c] = lo; vals[1][c] = hi;
            asm("mov.b64 {%0,%1}, %2;" : "=f"(lo), "=f"(hi) : "l"(acc[c][1]));
            vals[2][c] = lo; vals[3][c] = hi;
        }
#pragma unroll
        for (int ri = 0; ri < 4; ri++) {
            int r = ty4 + ri;
            const float4 pi = *(const float4*)(g_P + (size_t)idxs[r] * 576 + c0);
            const float4 pj = *(const float4*)(g_P + (size_t)NN * 576 + (size_t)idxs[64 + r] * 576 + c0);
            float4 o;
            o.x = vals[ri][0] + pi.x + pj.x + bb.x;
            o.y = vals[ri][1] + pi.y + pj.y + bb.y;
            o.z = vals[ri][2] + pi.z + pj.z + bb.z;
            o.w = vals[ri][3] + pi.w + pj.w + bb.w;
            *(float4*)(tbuf + (size_t)r * 576 + c0) = o;
        }
    }
    __syncthreads();

    // -------- Phase 2: relu + LayerNorm per segment --------
    const float inv256 = 1.0f / 256.0f, inv64 = 1.0f / 64.0f;
#pragma unroll 1
    for (int rr = 0; rr < 8; rr++) {
        int row = rr * 8 + wid;
        float* trow = tbuf + (size_t)row * 576;
        {   // seg1 -> h1 normalized, transposed+swizzled into ash
            float v[8], s = 0.f, q = 0.f;
#pragma unroll
            for (int j = 0; j < 8; j++) {
                float xv = fmaxf(trow[lane + j * 32], 0.f);
                v[j] = xv; s += xv; q += xv * xv;
            }
            s = warp_sum(s); q = warp_sum(q);
            float mu = s * inv256, rstd = rsqrtf(q * inv256 - mu * mu + EPS);
#pragma unroll
            for (int j = 0; j < 8; j++) {
                int c = lane + j * 32;
                ash[swz(c, row)] = (v[j] - mu) * rstd * g1[c] + be1[c];
            }
        }
        {   // seg2 -> att features, normalized IN PLACE (tbuf cols 256..319)
            float x0 = fmaxf(trow[256 + lane], 0.f), x1 = fmaxf(trow[288 + lane], 0.f);
            float s = warp_sum(x0 + x1), q = warp_sum(x0 * x0 + x1 * x1);
            float mu = s * inv64, rstd = rsqrtf(q * inv64 - mu * mu + EPS);
            trow[256 + lane] = (x0 - mu) * rstd * gatt[lane] + beatt[lane];
            trow[288 + lane] = (x1 - mu) * rstd * gatt[32 + lane] + beatt[32 + lane];
        }
        {   // seg3 -> new interaction features, straight to output
            float v[8], s = 0.f, q = 0.f;
#pragma unroll
            for (int j = 0; j < 8; j++) {
                float xv = fmaxf(trow[320 + lane + j * 32], 0.f);
                v[j] = xv; s += xv; q += xv * xv;
            }
            s = warp_sum(s); q = warp_sum(q);
            float mu = s * inv256, rstd = rsqrtf(q * inv256 - mu * mu + EPS);
            float* dst = out + 524288 + ((size_t)n * 64 + row) * 256;
#pragma unroll
            for (int j = 0; j < 8; j++) {
                int c = lane + j * 32;
                dst[c] = (v[j] - mu) * rstd * gif[c] + beif[c];
            }
        }
    }

    // -------- Phase 3: t2 = h1 @ w2 + b2  (4 x 64-col tiles into tbuf cols 320..575) --------
#pragma unroll 1
    for (int cc = 0; cc < 4; cc++) {
        const float* wsrc = w2 + cc * 64;
        float4 r0 = *(const float4*)(wsrc + wk * 256 + wc);
        float4 r1 = *(const float4*)(wsrc + wk * 256 + wc + 4);
        *(float4*)(wsh + wk * 68 + wc) = r0;
        *(float4*)(wsh + wk * 68 + wc + 4) = r1;
        __syncthreads();
        unsigned long long acc[4][2] = {{0ull,0ull},{0ull,0ull},{0ull,0ull},{0ull,0ull}};
#pragma unroll 1
        for (int kp = 0; kp < 8; kp++) {
            if (kp < 7) {
                const float* s = wsrc + (size_t)(kp + 1) * 32 * 256 + wk * 256 + wc;
                r0 = *(const float4*)s; r1 = *(const float4*)(s + 4);
            }
            micro32x2(asho + (unsigned)((kp * 32) << 8),
                      wsho + (unsigned)((kp & 1) * 8704) + tx16, ty16, acc);
            if (kp < 7) {
                float* d = wsh + ((kp + 1) & 1) * 2176 + wk * 68 + wc;
                *(float4*)d = r0; *(float4*)(d + 4) = r1;
                __syncthreads();
            }
        }
        int c0 = cc * 64 + tx4;
        float4 bb = *(const float4*)(b2 + c0);
        float vals[4][4];
#pragma unroll
        for (int c = 0; c < 4; c++) {
            float lo, hi;
            asm("mov.b64 {%0,%1}, %2;" : "=f"(lo), "=f"(hi) : "l"(acc[c][0]));
            vals[0][c] = lo; vals[1][c] = hi;
            asm("mov.b64 {%0,%1}, %2;" : "=f"(lo), "=f"(hi) : "l"(acc[c][1]));
            vals[2][c] = lo; vals[3][c] = hi;
        }
#pragma unroll
        for (int ri = 0; ri < 4; ri++) {
            int r = ty4 + ri;
            float4 o;
            o.x = vals[ri][0] + bb.x; o.y = vals[ri][1] + bb.y;
            o.z = vals[ri][2] + bb.z; o.w = vals[ri][3] + bb.w;
            *(float4*)(tbuf + (size_t)r * 576 + 320 + c0) = o;
        }
    }
    __syncthreads();

    // -------- Phase 4: h2 = LN(relu(t2)); logits -> slog --------
#pragma unroll 1
    for (int rr = 0; rr < 8; rr++) {
        int row = rr * 8 + wid;
        const float* trow = tbuf + (size_t)row * 576 + 320;
        float v[8], s = 0.f, q = 0.f;
#pragma unroll
        for (int j = 0; j < 8; j++) {
            float xv = fmaxf(trow[lane + j * 32], 0.f);
            v[j] = xv; s += xv; q += xv * xv;
        }
        s = warp_sum(s); q = warp_sum(q);
        float mu = s * inv256, rstd = rsqrtf(q * inv256 - mu * mu + EPS);
        float l0 = 0.f, l1 = 0.f, l2 = 0.f, l3 = 0.f;
#pragma unroll
        for (int j = 0; j < 8; j++) {
            int c = lane + j * 32;
            float y = (v[j] - mu) * rstd * g2[c] + be2[c];
            float4 wp = *(const float4*)(wpre + (size_t)c * 4);
            l0 += y * wp.x; l1 += y * wp.y; l2 += y * wp.z; l3 += y * wp.w;
        }
        l0 = warp_sum(l0); l1 = warp_sum(l1); l2 = warp_sum(l2); l3 = warp_sum(l3);
        if (lane == 0) {
            bool mk = mask[n * 64 + row] != 0;
            slog[row * 4 + 0] = mk ? NEG : (l0 + bpre[0]);
            slog[row * 4 + 1] = mk ? NEG : (l1 + bpre[1]);
            slog[row * 4 + 2] = mk ? NEG : (l2 + bpre[2]);
            slog[row * 4 + 3] = mk ? NEG : (l3 + bpre[3]);
        }
    }
    __syncthreads();

    // -------- Phase 5: per-head top-16 softmax -> wsm --------
    if (wid < 4) {
        int h = wid;
        float v0 = slog[lane * 4 + h], v1 = slog[(32 + lane) * 4 + h];
        float c0 = v0, c1 = v1;
        float thr = NEG, maxv = NEG;
#pragma unroll 1
        for (int it = 0; it < 16; it++) {
            float loc = fmaxf(c0, c1);
            float m = warp_max(loc);
            if (it == 0) maxv = m;
            if (m == NEG) break;
            thr = m;
            unsigned bl = __ballot_sync(0xffffffffu, loc == m);
            int src = __ffs(bl) - 1;
            if (lane == src) { if (c0 == m) c0 = NEG; else c1 = NEG; }
        }
        float e0 = (v0 >= thr) ? expf(v0 - maxv) : 0.f;
        float e1 = (v1 >= thr) ? expf(v1 - maxv) : 0.f;
        float inv = 1.f / warp_sum(e0 + e1);
        wsm[h * 64 + lane] = e0 * inv;
        wsm[h * 64 + 32 + lane] = e1 * inv;
    }
    __syncthreads();

    // -------- Phase 6: agg[d,h] = sum_m w[h,m] * af[m,d]  (af in tbuf cols 256..319) --------
    {
        int d = t >> 2, h = t & 3;
        float s = 0.f;
#pragma unroll
        for (int m = 0; m < 64; m++) s += wsm[h * 64 + m] * tbuf[(size_t)m * 576 + 256 + d];
        aggs[t] = s;
    }
    __syncthreads();

    // -------- Phase 7: x_out = LN(relu(agg @ wg + bg)) --------
    {
        float v0a = 0.f, v1a = 0.f, v2a = 0.f, v3a = 0.f;
#pragma unroll 4
        for (int k = 0; k < 256; k += 4) {
            v0a += aggs[k]     * wg[(size_t)k * 256 + t];
            v1a += aggs[k + 1] * wg[(size_t)(k + 1) * 256 + t];
            v2a += aggs[k + 2] * wg[(size_t)(k + 2) * 256 + t];
            v3a += aggs[k + 3] * wg[(size_t)(k + 3) * 256 + t];
        }
        float v = fmaxf((v0a + v1a) + (v2a + v3a) + bg[t], 0.f);
        float s = warp_sum(v), q = warp_sum(v * v);
        if (lane == 0) { red[wid] = s; red[8 + wid] = q; }
        __syncthreads();
        if (t < 32) {
            float a = (lane < 8) ? red[lane] : 0.f;
            float b = (lane < 8) ? red[8 + lane] : 0.f;
#pragma unroll
            for (int o = 4; o; o >>= 1) {
                a += __shfl_xor_sync(0xffffffffu, a, o);
                b += __shfl_xor_sync(0xffffffffu, b, o);
            }
            if (lane == 0) { red[0] = a; red[8] = b; }
        }
        __syncthreads();
        float mu = red[0] * (1.f / 256.f), rstd = rsqrtf(red[8] * (1.f / 256.f) - mu * mu + EPS);
        float y = (v - mu) * rstd * gg[t] + beg[t];
        out[(size_t)n * 256 + t] = y;                 // x_out
        out[34078720ull + (size_t)n * 256 + t] = y;   // m (== x_out)
    }
}

// ---------------- launch ----------------
extern "C" void kernel_launch(void* const* d_in, const int* in_sizes, int n_in,
                              void* d_out, int out_size) {
    const float* x = (const float*)d_in[0];
    const float* iff = (const float*)d_in[1];
    const int* mask = (const int*)d_in[2];
    const int* ai = (const int*)d_in[3];
    const int* aj = (const int*)d_in[4];
    const float* w1 = (const float*)d_in[5], *b1 = (const float*)d_in[6];
    const float* g1 = (const float*)d_in[7], *be1 = (const float*)d_in[8];
    const float* w2 = (const float*)d_in[9], *b2 = (const float*)d_in[10];
    const float* g2 = (const float*)d_in[11], *be2 = (const float*)d_in[12];
    const float* wpre = (const float*)d_in[13], *bpre = (const float*)d_in[14];
    const float* watt = (const float*)d_in[15], *batt = (const float*)d_in[16];
    const float* gatt = (const float*)d_in[17], *beatt = (const float*)d_in[18];
    const float* wif = (const float*)d_in[19], *bif = (const float*)d_in[20];
    const float* gif = (const float*)d_in[21], *beif = (const float*)d_in[22];
    const float* wg = (const float*)d_in[23], *bg = (const float*)d_in[24];
    const float* gg = (const float*)d_in[25], *beg = (const float*)d_in[26];
    float* out = (float*)d_out;

    const int PS = (256 * 65 + 32 * 65) * 4;
    const int BS = (36864 + 16384 + 4352) * 4 + 128 * 4;  // 230,912 B
    cudaFuncSetAttribute(p_kernel, cudaFuncAttributeMaxDynamicSharedMemorySize, PS);
    cudaFuncSetAttribute(big_kernel, cudaFuncAttributeMaxDynamicSharedMemorySize, BS);

    pack_kernel<<<1728, 256>>>(w1, watt, wif, b1, batt, bif);
    p_kernel<<<dim3(32, 2), 256, PS>>>(x);
    big_kernel<<<2048, 256, BS>>>(iff, ai, aj, g1, be1, gatt, beatt, gif, beif,
                                  w2, b2, g2, be2, wpre, bpre, mask,
                                  wg, bg, gg, beg, out);
}

// round 9
// speedup vs baseline: 1.0785x; 1.0785x over previous
#include <cuda_runtime.h>
#include <cuda_bf16.h>
#include <cstdint>
#include <cstddef>

#define NN 2048
#define EPS 1e-5f

// ---------------- device scratch ----------------
__device__ float g_Wcat[512 * 576];                        // x_i|x_j weight rows, packed cols
__device__ float g_bcat[576];                              // packed biases
__device__ float g_P[2 * NN * 576];                        // Pi, Pj tables
// 52 tiles x 3 images x (16 n x 256 k) bf16 = 52 x 12288 elems
__device__ __align__(16) __nv_bfloat16 g_Bt[52 * 12288];

__device__ __forceinline__ float warp_sum(float v) {
#pragma unroll
    for (int o = 16; o; o >>= 1) v += __shfl_xor_sync(0xffffffffu, v, o);
    return v;
}
__device__ __forceinline__ float warp_max(float v) {
#pragma unroll
    for (int o = 16; o; o >>= 1) v = fmaxf(v, __shfl_xor_sync(0xffffffffu, v, o));
    return v;
}

#define CP_COMMIT() asm volatile("cp.async.commit_group;" ::: "memory")
#define CP_WAIT1()  asm volatile("cp.async.wait_group 1;" ::: "memory")
#define CP_WAIT0()  asm volatile("cp.async.wait_group 0;" ::: "memory")

__device__ __forceinline__ void ldsm4(unsigned r[4], unsigned addr) {
    asm volatile("ldmatrix.sync.aligned.m8n8.x4.shared.b16 {%0,%1,%2,%3}, [%4];"
                 : "=r"(r[0]), "=r"(r[1]), "=r"(r[2]), "=r"(r[3]) : "r"(addr));
}
__device__ __forceinline__ void ldsm2(unsigned r[2], unsigned addr) {
    asm volatile("ldmatrix.sync.aligned.m8n8.x2.shared.b16 {%0,%1}, [%2];"
                 : "=r"(r[0]), "=r"(r[1]) : "r"(addr));
}
__device__ __forceinline__ void mma16816(float d[4], const unsigned a[4], const unsigned b[2]) {
    asm volatile("mma.sync.aligned.m16n8k16.row.col.f32.bf16.bf16.f32 "
                 "{%0,%1,%2,%3}, {%4,%5,%6,%7}, {%8,%9}, {%0,%1,%2,%3};"
                 : "+f"(d[0]), "+f"(d[1]), "+f"(d[2]), "+f"(d[3])
                 : "r"(a[0]), "r"(a[1]), "r"(a[2]), "r"(a[3]), "r"(b[0]), "r"(b[1]));
}

// 3-way bf16 split of fp32 (residuals exact in fp32)
__device__ __forceinline__ void split3(float a, __nv_bfloat16& a0, __nv_bfloat16& a1, __nv_bfloat16& a2) {
    a0 = __float2bfloat16_rn(a);
    float r1 = a - __bfloat162float(a0);
    a1 = __float2bfloat16_rn(r1);
    float r2 = r1 - __bfloat162float(a1);
    a2 = __float2bfloat16_rn(r2);
}
// pack pair (a,b) -> three bf16x2 words
__device__ __forceinline__ void pk3(float a, float b, uint32_t& w0, uint32_t& w1, uint32_t& w2) {
    __nv_bfloat16 a0, a1, a2, b0, b1, b2;
    split3(a, a0, a1, a2); split3(b, b0, b1, b2);
    w0 = ((uint32_t)__bfloat16_as_ushort(b0) << 16) | (uint32_t)__bfloat16_as_ushort(a0);
    w1 = ((uint32_t)__bfloat16_as_ushort(b1) << 16) | (uint32_t)__bfloat16_as_ushort(a1);
    w2 = ((uint32_t)__bfloat16_as_ushort(b2) << 16) | (uint32_t)__bfloat16_as_ushort(a2);
}

// tiles: 0-15 new_if(gc 320..575), 16-19 att(gc 256..319), 20-35 h1(gc 0..255), 36-51 w2
__device__ __host__ __forceinline__ int tile_gc(int tl) {
    return (tl < 16) ? 320 + tl * 16 : (tl < 20) ? 256 + (tl - 16) * 16
          : (tl < 36) ? (tl - 20) * 16 : (tl - 36) * 16;
}

// ---------------- K0: pack ----------------
__global__ void pack_kernel(const float* __restrict__ w1, const float* __restrict__ watt,
                            const float* __restrict__ wif, const float* __restrict__ b1,
                            const float* __restrict__ batt, const float* __restrict__ bif,
                            const float* __restrict__ w2) {
    int idx = blockIdx.x * blockDim.x + threadIdx.x;
    if (idx < 512 * 576) {
        int r = idx / 576, c = idx - r * 576;
        g_Wcat[idx] = (c < 256) ? w1[r * 256 + c]
                     : (c < 320) ? watt[r * 64 + (c - 256)]
                                 : wif[r * 256 + (c - 320)];
    }
    if (idx < 576)
        g_bcat[idx] = (idx < 256) ? b1[idx] : (idx < 320) ? batt[idx - 256] : bif[idx - 320];
    if (idx < 52 * 4096) {
        int tl = idx >> 12, rr = idx & 4095;
        int n = rr >> 8, k = rr & 255;   // n in 0..15, k in 0..255
        float w;
        if (tl < 36) {
            int c = tile_gc(tl) + n, r = 512 + k;
            w = (c < 256) ? w1[r * 256 + c]
               : (c < 320) ? watt[r * 64 + (c - 256)]
                           : wif[r * 256 + (c - 320)];
        } else {
            w = w2[k * 256 + (tl - 36) * 16 + n];
        }
        __nv_bfloat16 v0, v1, v2;
        split3(w, v0, v1, v2);
        int byte = n * 512 + ((k * 2) ^ ((n & 7) << 4));   // 16B-chunk XOR swizzle
        size_t base = (size_t)tl * 12288 + (byte >> 1);
        g_Bt[base] = v0;
        g_Bt[base + 4096] = v1;
        g_Bt[base + 8192] = v2;
    }
}

// ---------------- K1: P = x @ Wcat(part) ----------------
__device__ __forceinline__ void micro_fma32(const float* __restrict__ ap,
                                            const float* __restrict__ bp, float acc[4][4]) {
#pragma unroll 8
    for (int k = 0; k < 32; k++) {
        const float* apk = ap + k * 65;
        const float* bpk = bp + k * 65;
        float a0 = apk[0], a1 = apk[1], a2 = apk[2], a3 = apk[3];
        float b0 = bpk[0], b1 = bpk[1], b2 = bpk[2], b3 = bpk[3];
        acc[0][0] += a0*b0; acc[0][1] += a0*b1; acc[0][2] += a0*b2; acc[0][3] += a0*b3;
        acc[1][0] += a1*b0; acc[1][1] += a1*b1; acc[1][2] += a1*b2; acc[1][3] += a1*b3;
        acc[2][0] += a2*b0; acc[2][1] += a2*b1; acc[2][2] += a2*b2; acc[2][3] += a2*b3;
        acc[3][0] += a3*b0; acc[3][1] += a3*b1; acc[3][2] += a3*b2; acc[3][3] += a3*b3;
    }
}
__global__ void __launch_bounds__(256) p_kernel(const float* __restrict__ x) {
    extern __shared__ float sm[];
    float* xs = sm;
    float* wsh = xs + 256 * 65;
    int nb = blockIdx.x, part = blockIdx.y, cg = blockIdx.z;
    int t = threadIdx.x, ty = t >> 4, tx = t & 15;
    {
        int row = t >> 2, k0 = (t & 3) * 64;
        const float* src = x + (size_t)(nb * 64 + row) * 256 + k0;
#pragma unroll
        for (int k = 0; k < 64; k += 4) {
            float4 v = *(const float4*)(src + k);
            xs[(k0+k)*65+row]=v.x; xs[(k0+k+1)*65+row]=v.y;
            xs[(k0+k+2)*65+row]=v.z; xs[(k0+k+3)*65+row]=v.w;
        }
    }
    __syncthreads();
    for (int cc = cg * 3; cc < cg * 3 + 3; cc++) {
        float acc[4][4] = {};
        for (int kp = 0; kp < 8; kp++) {
            {
                int k = t >> 3, cb = (t & 7) * 8;
                const float* src = g_Wcat + (size_t)(part*256 + kp*32 + k)*576 + cc*64 + cb;
                float4 v0 = *(const float4*)src, v1 = *(const float4*)(src + 4);
                float* d = wsh + k*65 + cb;
                d[0]=v0.x; d[1]=v0.y; d[2]=v0.z; d[3]=v0.w;
                d[4]=v1.x; d[5]=v1.y; d[6]=v1.z; d[7]=v1.w;
            }
            __syncthreads();
            micro_fma32(xs + kp*32*65 + ty*4, wsh + tx*4, acc);
            __syncthreads();
        }
#pragma unroll
        for (int ri = 0; ri < 4; ri++) {
            float4 v = make_float4(acc[ri][0], acc[ri][1], acc[ri][2], acc[ri][3]);
            *(float4*)(g_P + (size_t)part*NN*576 + (size_t)(nb*64 + ty*4 + ri)*576 + cc*64 + tx*4) = v;
        }
    }
}

// ---------------- K2: fused per-site kernel ----------------
// smem (bytes): [16..528) idxs; A imgs at 1024/33792/66560 (32KB each);
// B dbl buf 99328/123904 (24576 each); tbuf 148480 [64][260] fp32; afb 215040 [64][66].
__global__ void __launch_bounds__(256) big_kernel(
    const float* __restrict__ IF, const int* __restrict__ ai, const int* __restrict__ aj,
    const float* __restrict__ g1, const float* __restrict__ be1,
    const float* __restrict__ gatt, const float* __restrict__ beatt,
    const float* __restrict__ gif, const float* __restrict__ beif,
    const float* __restrict__ b2, const float* __restrict__ g2, const float* __restrict__ be2,
    const float* __restrict__ wpre, const float* __restrict__ bpre,
    const int* __restrict__ mask,
    const float* __restrict__ wg, const float* __restrict__ bg,
    const float* __restrict__ gg, const float* __restrict__ beg,
    float* __restrict__ out) {
    extern __shared__ char smem[];
    const unsigned sb = (unsigned)__cvta_generic_to_shared(smem);
    int* idxs = (int*)(smem + 16);
    char* Agen = smem + 1024;
    const unsigned Abase = sb + 1024;
    const unsigned Bb[2] = { sb + 99328, sb + 123904 };
    float* tbuf = (float*)(smem + 148480);   // [64][260]
    float* afb  = (float*)(smem + 215040);   // [64][66]
    float* slog = (float*)(smem + 99328);    // aliases, used after GEMMs
    float* wsm  = (float*)(smem + 100352);
    float* aggs = (float*)(smem + 101376);
    float* red  = (float*)(smem + 102400);

    const int n = blockIdx.x, t = threadIdx.x;
    const int lane = t & 31, wid = t >> 5;
    const int mrow0 = (wid >> 1) << 4;       // M16 group
    const int nhalf = (wid & 1) << 3;        // n8 half within 16-col tile
    const float NEG = __int_as_float(0xff800000);
    const float inv256 = 1.f / 256.f, inv64 = 1.f / 64.f;

    // ldmatrix geometry
    const int arow = mrow0 + (lane & 15);
    const unsigned abase_off = (unsigned)(arow * 512);
    const unsigned asw = (unsigned)((arow & 7) << 4);
    const unsigned achunk = (unsigned)((lane >> 4) << 4);
    const int brow = nhalf + (lane & 7);
    const unsigned bbase_off = (unsigned)(brow * 512);
    const unsigned bsw = (unsigned)((brow & 7) << 4);
    const unsigned bchunk = (unsigned)(((lane >> 3) & 1) << 4);

    if (t < 64) { idxs[t] = ai[n * 64 + t]; idxs[64 + t] = aj[n * 64 + t]; }

    // prefetch B tile 0 (24576 B)
    {
        const char* src = (const char*)g_Bt;
#pragma unroll
        for (int i = 0; i < 6; i++) {
            unsigned off = (unsigned)(i * 4096 + t * 16);
            asm volatile("cp.async.cg.shared.global [%0], [%1], 16;" :: "r"(Bb[0] + off), "l"(src + off) : "memory");
        }
        CP_COMMIT();
    }

    // convert IF -> A (3 bf16 images, swizzled)
    {
        int row = t >> 2, k0 = (t & 3) * 64;
        const float* src = IF + (size_t)(n * 64 + row) * 256 + k0;
#pragma unroll
        for (int c = 0; c < 8; c++) {
            float4 v0 = *(const float4*)(src + c * 8);
            float4 v1 = *(const float4*)(src + c * 8 + 4);
            uint4 i0, i1, i2;
            pk3(v0.x, v0.y, i0.x, i1.x, i2.x);
            pk3(v0.z, v0.w, i0.y, i1.y, i2.y);
            pk3(v1.x, v1.y, i0.z, i1.z, i2.z);
            pk3(v1.z, v1.w, i0.w, i1.w, i2.w);
            unsigned off = (unsigned)(row * 512 + (((k0 + c * 8) * 2) ^ ((row & 7) << 4)));
            *(uint4*)(Agen + off) = i0;
            *(uint4*)(Agen + 32768 + off) = i1;
            *(uint4*)(Agen + 65536 + off) = i2;
        }
    }

    // ================= main tile loop =================
#pragma unroll 1
    for (int tl = 0; tl < 52; tl++) {
        if (tl < 51) {
            const char* src = (const char*)g_Bt + (size_t)(tl + 1) * 24576;
            unsigned dst = Bb[(tl + 1) & 1];
#pragma unroll
            for (int i = 0; i < 6; i++) {
                unsigned off = (unsigned)(i * 4096 + t * 16);
                asm volatile("cp.async.cg.shared.global [%0], [%1], 16;" :: "r"(dst + off), "l"(src + off) : "memory");
            }
            CP_COMMIT();
            CP_WAIT1();
        } else {
            CP_WAIT0();
        }
        __syncthreads();

        const bool six = (tl >= 20);   // h1 + GEMM2 tiles use 6-term split
        float dd[6][4] = {};
        const unsigned Bt0 = Bb[tl & 1];
#pragma unroll 4
        for (int ks = 0; ks < 16; ks++) {
            unsigned kb = (unsigned)(ks << 5);
            unsigned aoff = abase_off + ((kb + achunk) ^ asw);
            unsigned boff = bbase_off + ((kb + bchunk) ^ bsw);
            unsigned a0[4], a1[4], b0[2], b1[2];
            ldsm4(a0, Abase + aoff);
            ldsm4(a1, Abase + 32768 + aoff);
            ldsm2(b0, Bt0 + boff);
            ldsm2(b1, Bt0 + 8192 + boff);
            mma16816(dd[0], a0, b0);
            mma16816(dd[1], a1, b0);
            mma16816(dd[2], a0, b1);
            if (six) {
                unsigned a2[4], b2r[2];
                ldsm4(a2, Abase + 65536 + aoff);
                ldsm2(b2r, Bt0 + 16384 + boff);
                mma16816(dd[3], a1, b1);
                mma16816(dd[4], a2, b0);
                mma16816(dd[5], a0, b2r);
            }
        }

        // ---- epilogue ----
        {
            int g = lane >> 2, tig = lane & 3;
            int lc = nhalf + 2 * tig;
            float e0 = dd[0][0] + dd[1][0] + dd[2][0];
            float e1 = dd[0][1] + dd[1][1] + dd[2][1];
            float e2 = dd[0][2] + dd[1][2] + dd[2][2];
            float e3 = dd[0][3] + dd[1][3] + dd[2][3];
            if (six) {
                e0 += dd[3][0] + dd[4][0] + dd[5][0];
                e1 += dd[3][1] + dd[4][1] + dd[5][1];
                e2 += dd[3][2] + dd[4][2] + dd[5][2];
                e3 += dd[3][3] + dd[4][3] + dd[5][3];
            }
            float* dst; int dstride, dcol;
            if (tl < 16)      { dst = tbuf; dstride = 260; dcol = tl * 16; }
            else if (tl < 20) { dst = afb;  dstride = 66;  dcol = (tl - 16) * 16; }
            else if (tl < 36) { dst = tbuf; dstride = 260; dcol = (tl - 20) * 16; }
            else              { dst = tbuf; dstride = 260; dcol = (tl - 36) * 16; }
            int colg = tile_gc(tl) + lc;
            int dc = dcol + lc;
            int r0 = mrow0 + g, r1 = r0 + 8;
            if (tl < 36) {
                float2 bb = *(const float2*)(g_bcat + colg);
                float2 pi0 = *(const float2*)(g_P + (size_t)idxs[r0] * 576 + colg);
                float2 pj0 = *(const float2*)(g_P + (size_t)NN * 576 + (size_t)idxs[64 + r0] * 576 + colg);
                float2 pi1 = *(const float2*)(g_P + (size_t)idxs[r1] * 576 + colg);
                float2 pj1 = *(const float2*)(g_P + (size_t)NN * 576 + (size_t)idxs[64 + r1] * 576 + colg);
                *(float2*)(dst + (size_t)r0 * dstride + dc) =
                    make_float2(e0 + pi0.x + pj0.x + bb.x, e1 + pi0.y + pj0.y + bb.y);
                *(float2*)(dst + (size_t)r1 * dstride + dc) =
                    make_float2(e2 + pi1.x + pj1.x + bb.x, e3 + pi1.y + pj1.y + bb.y);
            } else {
                float2 bb = *(const float2*)(b2 + colg);
                *(float2*)(dst + (size_t)r0 * dstride + dc) = make_float2(e0 + bb.x, e1 + bb.y);
                *(float2*)(dst + (size_t)r1 * dstride + dc) = make_float2(e2 + bb.x, e3 + bb.y);
            }
        }

        // ---- segment boundaries ----
        if (tl == 15) {
            __syncthreads();
            // LN new_if -> out
#pragma unroll 1
            for (int rr = 0; rr < 8; rr++) {
                int row = rr * 8 + wid;
                const float* trow = tbuf + row * 260;
                float v[8], s = 0.f, qq = 0.f;
#pragma unroll
                for (int j = 0; j < 8; j++) {
                    float xv = fmaxf(trow[lane + j * 32], 0.f);
                    v[j] = xv; s += xv; qq += xv * xv;
                }
                s = warp_sum(s); qq = warp_sum(qq);
                float mu = s * inv256, rstd = rsqrtf(qq * inv256 - mu * mu + EPS);
                float* o = out + 524288 + ((size_t)n * 64 + row) * 256;
#pragma unroll
                for (int j = 0; j < 8; j++) {
                    int c = lane + j * 32;
                    o[c] = (v[j] - mu) * rstd * gif[c] + beif[c];
                }
            }
        }
        if (tl == 35) {
            __syncthreads();
            // LN att (afb in place) + LN h1 (tbuf in place)
#pragma unroll 1
            for (int rr = 0; rr < 8; rr++) {
                int row = rr * 8 + wid;
                {
                    float* ar = afb + row * 66;
                    float x0 = fmaxf(ar[lane], 0.f), x1 = fmaxf(ar[32 + lane], 0.f);
                    float s = warp_sum(x0 + x1), qq = warp_sum(x0 * x0 + x1 * x1);
                    float mu = s * inv64, rstd = rsqrtf(qq * inv64 - mu * mu + EPS);
                    ar[lane] = (x0 - mu) * rstd * gatt[lane] + beatt[lane];
                    ar[32 + lane] = (x1 - mu) * rstd * gatt[32 + lane] + beatt[32 + lane];
                }
                {
                    float* trow = tbuf + row * 260;
                    float v[8], s = 0.f, qq = 0.f;
#pragma unroll
                    for (int j = 0; j < 8; j++) {
                        float xv = fmaxf(trow[lane + j * 32], 0.f);
                        v[j] = xv; s += xv; qq += xv * xv;
                    }
                    s = warp_sum(s); qq = warp_sum(qq);
                    float mu = s * inv256, rstd = rsqrtf(qq * inv256 - mu * mu + EPS);
#pragma unroll
                    for (int j = 0; j < 8; j++) {
                        int c = lane + j * 32;
                        trow[c] = (v[j] - mu) * rstd * g1[c] + be1[c];
                    }
                }
            }
            __syncthreads();
            // rewrite A = h1 (3 bf16 images)
            {
                int row = t >> 2, k0 = (t & 3) * 64;
                const float* src = tbuf + row * 260 + k0;
#pragma unroll
                for (int c = 0; c < 8; c++) {
                    float4 v0 = *(const float4*)(src + c * 8);
                    float4 v1 = *(const float4*)(src + c * 8 + 4);
                    uint4 i0, i1, i2;
                    pk3(v0.x, v0.y, i0.x, i1.x, i2.x);
                    pk3(v0.z, v0.w, i0.y, i1.y, i2.y);
                    pk3(v1.x, v1.y, i0.z, i1.z, i2.z);
                    pk3(v1.z, v1.w, i0.w, i1.w, i2.w);
                    unsigned off = (unsigned)(row * 512 + (((k0 + c * 8) * 2) ^ ((row & 7) << 4)));
                    *(uint4*)(Agen + off) = i0;
                    *(uint4*)(Agen + 32768 + off) = i1;
                    *(uint4*)(Agen + 65536 + off) = i2;
                }
            }
        }
        __syncthreads();   // guard B-buffer rotate + A visibility
    }

    // ---- Phase 4: h2 = LN(relu(t2)); logits -> slog ----
#pragma unroll 1
    for (int rr = 0; rr < 8; rr++) {
        int row = rr * 8 + wid;
        const float* trow = tbuf + row * 260;
        float v[8], s = 0.f, qq = 0.f;
#pragma unroll
        for (int j = 0; j < 8; j++) {
            float xv = fmaxf(trow[lane + j * 32], 0.f);
            v[j] = xv; s += xv; qq += xv * xv;
        }
        s = warp_sum(s); qq = warp_sum(qq);
        float mu = s * inv256, rstd = rsqrtf(qq * inv256 - mu * mu + EPS);
        float l0 = 0.f, l1 = 0.f, l2 = 0.f, l3 = 0.f;
#pragma unroll
        for (int j = 0; j < 8; j++) {
            int c = lane + j * 32;
            float y = (v[j] - mu) * rstd * g2[c] + be2[c];
            float4 wp = *(const float4*)(wpre + (size_t)c * 4);
            l0 += y * wp.x; l1 += y * wp.y; l2 += y * wp.z; l3 += y * wp.w;
        }
        l0 = warp_sum(l0); l1 = warp_sum(l1); l2 = warp_sum(l2); l3 = warp_sum(l3);
        if (lane == 0) {
            bool mk = mask[n * 64 + row] != 0;
            slog[row * 4 + 0] = mk ? NEG : (l0 + bpre[0]);
            slog[row * 4 + 1] = mk ? NEG : (l1 + bpre[1]);
            slog[row * 4 + 2] = mk ? NEG : (l2 + bpre[2]);
            slog[row * 4 + 3] = mk ? NEG : (l3 + bpre[3]);
        }
    }
    __syncthreads();

    // ---- Phase 5: per-head top-16 softmax ----
    if (wid < 4) {
        int h = wid;
        float v0 = slog[lane * 4 + h], v1 = slog[(32 + lane) * 4 + h];
        float c0 = v0, c1 = v1;
        float thr = NEG, maxv = NEG;
#pragma unroll 1
        for (int it = 0; it < 16; it++) {
            float loc = fmaxf(c0, c1);
            float m = warp_max(loc);
            if (it == 0) maxv = m;
            if (m == NEG) break;
            thr = m;
            unsigned bl = __ballot_sync(0xffffffffu, loc == m);
            int src = __ffs(bl) - 1;
            if (lane == src) { if (c0 == m) c0 = NEG; else c1 = NEG; }
        }
        float e0 = (v0 >= thr) ? expf(v0 - maxv) : 0.f;
        float e1 = (v1 >= thr) ? expf(v1 - maxv) : 0.f;
        float inv = 1.f / warp_sum(e0 + e1);
        wsm[h * 64 + lane] = e0 * inv;
        wsm[h * 64 + 32 + lane] = e1 * inv;
    }
    __syncthreads();

    // ---- Phase 6: agg[d,h] = sum_m w[h,m] * af[m,d] ----
    {
        int d = t >> 2, h = t & 3;
        float s = 0.f;
#pragma unroll
        for (int m = 0; m < 64; m++) s += wsm[h * 64 + m] * afb[m * 66 + d];
        aggs[t] = s;
    }
    __syncthreads();

    // ---- Phase 7: x_out = LN(relu(agg @ wg + bg)) ----
    {
        float v0a = 0.f, v1a = 0.f, v2a = 0.f, v3a = 0.f;
#pragma unroll 4
        for (int k = 0; k < 256; k += 4) {
            v0a += aggs[k]     * wg[(size_t)k * 256 + t];
            v1a += aggs[k + 1] * wg[(size_t)(k + 1) * 256 + t];
            v2a += aggs[k + 2] * wg[(size_t)(k + 2) * 256 + t];
            v3a += aggs[k + 3] * wg[(size_t)(k + 3) * 256 + t];
        }
        float v = fmaxf((v0a + v1a) + (v2a + v3a) + bg[t], 0.f);
        float s = warp_sum(v), qq = warp_sum(v * v);
        if (lane == 0) { red[wid] = s; red[8 + wid] = qq; }
        __syncthreads();
        if (t < 32) {
            float a = (lane < 8) ? red[lane] : 0.f;
            float b = (lane < 8) ? red[8 + lane] : 0.f;
#pragma unroll
            for (int o = 4; o; o >>= 1) {
                a += __shfl_xor_sync(0xffffffffu, a, o);
                b += __shfl_xor_sync(0xffffffffu, b, o);
            }
            if (lane == 0) { red[0] = a; red[8] = b; }
        }
        __syncthreads();
        float mu = red[0] * inv256, rstd = rsqrtf(red[8] * inv256 - mu * mu + EPS);
        float y = (v - mu) * rstd * gg[t] + beg[t];
        out[(size_t)n * 256 + t] = y;
        out[34078720ull + (size_t)n * 256 + t] = y;
    }
}

// ---------------- launch ----------------
extern "C" void kernel_launch(void* const* d_in, const int* in_sizes, int n_in,
                              void* d_out, int out_size) {
    const float* x = (const float*)d_in[0];
    const float* iff = (const float*)d_in[1];
    const int* mask = (const int*)d_in[2];
    const int* ai = (const int*)d_in[3];
    const int* aj = (const int*)d_in[4];
    const float* w1 = (const float*)d_in[5], *b1 = (const float*)d_in[6];
    const float* g1 = (const float*)d_in[7], *be1 = (const float*)d_in[8];
    const float* w2 = (const float*)d_in[9], *b2 = (const float*)d_in[10];
    const float* g2 = (const float*)d_in[11], *be2 = (const float*)d_in[12];
    const float* wpre = (const float*)d_in[13], *bpre = (const float*)d_in[14];
    const float* watt = (const float*)d_in[15], *batt = (const float*)d_in[16];
    const float* gatt = (const float*)d_in[17], *beatt = (const float*)d_in[18];
    const float* wif = (const float*)d_in[19], *bif = (const float*)d_in[20];
    const float* gif = (const float*)d_in[21], *beif = (const float*)d_in[22];
    const float* wg = (const float*)d_in[23], *bg = (const float*)d_in[24];
    const float* gg = (const float*)d_in[25], *beg = (const float*)d_in[26];
    float* out = (float*)d_out;

    const int PS = (256 * 65 + 32 * 65) * 4;
    const int BS = 231936;
    cudaFuncSetAttribute(p_kernel, cudaFuncAttributeMaxDynamicSharedMemorySize, PS);
    cudaFuncSetAttribute(big_kernel, cudaFuncAttributeMaxDynamicSharedMemorySize, BS);

    pack_kernel<<<1152, 256>>>(w1, watt, wif, b1, batt, bif, w2);
    p_kernel<<<dim3(32, 2, 3), 256, PS>>>(x);
    big_kernel<<<2048, 256, BS>>>(iff, ai, aj, g1, be1, gatt, beatt, gif, beif,
                                  b2, g2, be2, wpre, bpre, mask,
                                  wg, bg, gg, beg, out);
}

// round 10
// speedup vs baseline: 1.5710x; 1.4567x over previous
#include <cuda_runtime.h>
#include <cuda_fp16.h>
#include <cstdint>
#include <cstddef>

#define NN 2048
#define EPS 1e-5f

// ---------------- device scratch ----------------
__device__ float g_Wcat[512 * 576];                 // x_i|x_j weight rows, packed cols
__device__ float g_bcat[576];                       // packed biases
__device__ float g_P[2 * NN * 576];                 // Pi, Pj tables
// 26 tiles x 2 images x (32 n x 256 k) fp16 = 26 x 16384 elems
__device__ __align__(16) __half g_Bt[26 * 16384];

__device__ __forceinline__ float warp_sum(float v) {
#pragma unroll
    for (int o = 16; o; o >>= 1) v += __shfl_xor_sync(0xffffffffu, v, o);
    return v;
}
__device__ __forceinline__ float warp_max(float v) {
#pragma unroll
    for (int o = 16; o; o >>= 1) v = fmaxf(v, __shfl_xor_sync(0xffffffffu, v, o));
    return v;
}

#define CP_COMMIT() asm volatile("cp.async.commit_group;" ::: "memory")
#define CP_WAIT1()  asm volatile("cp.async.wait_group 1;" ::: "memory")
#define CP_WAIT0()  asm volatile("cp.async.wait_group 0;" ::: "memory")

__device__ __forceinline__ void ldsm4(unsigned r[4], unsigned addr) {
    asm volatile("ldmatrix.sync.aligned.m8n8.x4.shared.b16 {%0,%1,%2,%3}, [%4];"
                 : "=r"(r[0]), "=r"(r[1]), "=r"(r[2]), "=r"(r[3]) : "r"(addr));
}
__device__ __forceinline__ void mma16816h(float d[4], const unsigned a[4], const unsigned b[2]) {
    asm volatile("mma.sync.aligned.m16n8k16.row.col.f32.f16.f16.f32 "
                 "{%0,%1,%2,%3}, {%4,%5,%6,%7}, {%8,%9}, {%0,%1,%2,%3};"
                 : "+f"(d[0]), "+f"(d[1]), "+f"(d[2]), "+f"(d[3])
                 : "r"(a[0]), "r"(a[1]), "r"(a[2]), "r"(a[3]), "r"(b[0]), "r"(b[1]));
}

// 2-way fp16 split of an fp32 pair -> two packed half2 words (hi image, residual image)
__device__ __forceinline__ void split2h(float a, float b, uint32_t& w0, uint32_t& w1) {
    __half a0 = __float2half_rn(a), b0 = __float2half_rn(b);
    __half a1 = __float2half_rn(a - __half2float(a0));
    __half b1 = __float2half_rn(b - __half2float(b0));
    w0 = ((uint32_t)__half_as_ushort(b0) << 16) | (uint32_t)__half_as_ushort(a0);
    w1 = ((uint32_t)__half_as_ushort(b1) << 16) | (uint32_t)__half_as_ushort(a1);
}

// 32-col tiles: 0-7 new_if(gc 320..575), 8-9 att(gc 256..319), 10-17 h1(gc 0..255), 18-25 w2
__device__ __host__ __forceinline__ int tile_gc(int tl) {
    return (tl < 8) ? 320 + tl * 32 : (tl < 10) ? 256 + (tl - 8) * 32
          : (tl < 18) ? (tl - 10) * 32 : (tl - 18) * 32;
}

// ---------------- K0: pack ----------------
__global__ void pack_kernel(const float* __restrict__ w1, const float* __restrict__ watt,
                            const float* __restrict__ wif, const float* __restrict__ b1,
                            const float* __restrict__ batt, const float* __restrict__ bif,
                            const float* __restrict__ w2) {
    int idx = blockIdx.x * blockDim.x + threadIdx.x;
    if (idx < 512 * 576) {
        int r = idx / 576, c = idx - r * 576;
        g_Wcat[idx] = (c < 256) ? w1[r * 256 + c]
                     : (c < 320) ? watt[r * 64 + (c - 256)]
                                 : wif[r * 256 + (c - 320)];
    }
    if (idx < 576)
        g_bcat[idx] = (idx < 256) ? b1[idx] : (idx < 320) ? batt[idx - 256] : bif[idx - 320];
    if (idx < 26 * 8192) {
        int tl = idx >> 13, rr = idx & 8191;
        int n = rr >> 8, k = rr & 255;   // n in 0..31, k in 0..255
        float w;
        if (tl < 18) {
            int c = tile_gc(tl) + n, r = 512 + k;
            w = (c < 256) ? w1[r * 256 + c]
               : (c < 320) ? watt[r * 64 + (c - 256)]
                           : wif[r * 256 + (c - 320)];
        } else {
            w = w2[k * 256 + (tl - 18) * 32 + n];
        }
        __half v0 = __float2half_rn(w);
        __half v1 = __float2half_rn(w - __half2float(v0));
        int byte = n * 512 + ((k * 2) ^ ((n & 7) << 4));   // 16B-chunk XOR swizzle
        size_t base = (size_t)tl * 16384 + (byte >> 1);
        g_Bt[base] = v0;
        g_Bt[base + 8192] = v1;
    }
}

// ---------------- K1: P = x @ Wcat(part) ----------------
__device__ __forceinline__ void micro_fma32(const float* __restrict__ ap,
                                            const float* __restrict__ bp, float acc[4][4]) {
#pragma unroll 8
    for (int k = 0; k < 32; k++) {
        const float* apk = ap + k * 65;
        const float* bpk = bp + k * 65;
        float a0 = apk[0], a1 = apk[1], a2 = apk[2], a3 = apk[3];
        float b0 = bpk[0], b1 = bpk[1], b2 = bpk[2], b3 = bpk[3];
        acc[0][0] += a0*b0; acc[0][1] += a0*b1; acc[0][2] += a0*b2; acc[0][3] += a0*b3;
        acc[1][0] += a1*b0; acc[1][1] += a1*b1; acc[1][2] += a1*b2; acc[1][3] += a1*b3;
        acc[2][0] += a2*b0; acc[2][1] += a2*b1; acc[2][2] += a2*b2; acc[2][3] += a2*b3;
        acc[3][0] += a3*b0; acc[3][1] += a3*b1; acc[3][2] += a3*b2; acc[3][3] += a3*b3;
    }
}
__global__ void __launch_bounds__(256) p_kernel(const float* __restrict__ x) {
    extern __shared__ float sm[];
    float* xs = sm;
    float* wsh = xs + 256 * 65;
    int nb = blockIdx.x, part = blockIdx.y, cg = blockIdx.z;
    int t = threadIdx.x, ty = t >> 4, tx = t & 15;
    {
        int row = t >> 2, k0 = (t & 3) * 64;
        const float* src = x + (size_t)(nb * 64 + row) * 256 + k0;
#pragma unroll
        for (int k = 0; k < 64; k += 4) {
            float4 v = *(const float4*)(src + k);
            xs[(k0+k)*65+row]=v.x; xs[(k0+k+1)*65+row]=v.y;
            xs[(k0+k+2)*65+row]=v.z; xs[(k0+k+3)*65+row]=v.w;
        }
    }
    __syncthreads();
    for (int cc = cg * 3; cc < cg * 3 + 3; cc++) {
        float acc[4][4] = {};
        for (int kp = 0; kp < 8; kp++) {
            {
                int k = t >> 3, cb = (t & 7) * 8;
                const float* src = g_Wcat + (size_t)(part*256 + kp*32 + k)*576 + cc*64 + cb;
                float4 v0 = *(const float4*)src, v1 = *(const float4*)(src + 4);
                float* d = wsh + k*65 + cb;
                d[0]=v0.x; d[1]=v0.y; d[2]=v0.z; d[3]=v0.w;
                d[4]=v1.x; d[5]=v1.y; d[6]=v1.z; d[7]=v1.w;
            }
            __syncthreads();
            micro_fma32(xs + kp*32*65 + ty*4, wsh + tx*4, acc);
            __syncthreads();
        }
#pragma unroll
        for (int ri = 0; ri < 4; ri++) {
            float4 v = make_float4(acc[ri][0], acc[ri][1], acc[ri][2], acc[ri][3]);
            *(float4*)(g_P + (size_t)part*NN*576 + (size_t)(nb*64 + ty*4 + ri)*576 + cc*64 + tx*4) = v;
        }
    }
}

// ---------------- K2: fused per-site kernel ----------------
// smem (bytes): [16..528) idxs; A imgs at 1024 / 33792 (32KB each);
// B dbl buf 66560 / 99328 (32768 each); tbuf 132096 [64][260] fp32; afb 198656 [64][66].
__global__ void __launch_bounds__(256) big_kernel(
    const float* __restrict__ IF, const int* __restrict__ ai, const int* __restrict__ aj,
    const float* __restrict__ g1, const float* __restrict__ be1,
    const float* __restrict__ gatt, const float* __restrict__ beatt,
    const float* __restrict__ gif, const float* __restrict__ beif,
    const float* __restrict__ b2, const float* __restrict__ g2, const float* __restrict__ be2,
    const float* __restrict__ wpre, const float* __restrict__ bpre,
    const int* __restrict__ mask,
    const float* __restrict__ wg, const float* __restrict__ bg,
    const float* __restrict__ gg, const float* __restrict__ beg,
    float* __restrict__ out) {
    extern __shared__ char smem[];
    const unsigned sb = (unsigned)__cvta_generic_to_shared(smem);
    int* idxs = (int*)(smem + 16);
    char* Agen = smem + 1024;
    const unsigned Abase = sb + 1024;
    const unsigned Bb[2] = { sb + 66560, sb + 99328 };
    float* tbuf = (float*)(smem + 132096);   // [64][260]
    float* afb  = (float*)(smem + 198656);   // [64][66]
    float* slog = (float*)(smem + 66560);    // aliases, used after GEMMs
    float* wsm  = (float*)(smem + 67584);
    float* aggs = (float*)(smem + 68608);
    float* red  = (float*)(smem + 69632);

    const int n = blockIdx.x, t = threadIdx.x;
    const int lane = t & 31, wid = t >> 5;
    const int mrow0 = (wid >> 1) << 4;       // M16 group (4 groups across warp pairs)
    const int nh16 = (wid & 1) << 4;         // N16 half within 32-col tile
    const float NEG = __int_as_float(0xff800000);
    const float inv256 = 1.f / 256.f, inv64 = 1.f / 64.f;

    // ldmatrix geometry: A fragment (m16k16)
    const int arow = mrow0 + (lane & 15);
    const unsigned abase_off = (unsigned)(arow * 512);
    const unsigned asw = (unsigned)((arow & 7) << 4);
    const unsigned achunk = (unsigned)((lane >> 4) << 4);
    // B fragment (n16k16): lanes 0-7 n0-7/k0, 8-15 n0-7/k8, 16-23 n8-15/k0, 24-31 n8-15/k8
    const int brow = nh16 + ((lane >> 4) << 3) + (lane & 7);
    const unsigned bbase_off = (unsigned)(brow * 512);
    const unsigned bsw = (unsigned)((brow & 7) << 4);
    const unsigned bchunk = (unsigned)(((lane >> 3) & 1) << 4);

    if (t < 64) { idxs[t] = ai[n * 64 + t]; idxs[64 + t] = aj[n * 64 + t]; }

    // prefetch B tile 0 (32768 B)
    {
        const char* src = (const char*)g_Bt;
#pragma unroll
        for (int i = 0; i < 8; i++) {
            unsigned off = (unsigned)(i * 4096 + t * 16);
            asm volatile("cp.async.cg.shared.global [%0], [%1], 16;" :: "r"(Bb[0] + off), "l"(src + off) : "memory");
        }
        CP_COMMIT();
    }

    // convert IF -> A (2 fp16 images, swizzled)
    {
        int row = t >> 2, k0 = (t & 3) * 64;
        const float* src = IF + (size_t)(n * 64 + row) * 256 + k0;
#pragma unroll
        for (int c = 0; c < 8; c++) {
            float4 v0 = *(const float4*)(src + c * 8);
            float4 v1 = *(const float4*)(src + c * 8 + 4);
            uint4 i0, i1;
            split2h(v0.x, v0.y, i0.x, i1.x);
            split2h(v0.z, v0.w, i0.y, i1.y);
            split2h(v1.x, v1.y, i0.z, i1.z);
            split2h(v1.z, v1.w, i0.w, i1.w);
            unsigned off = (unsigned)(row * 512 + (((k0 + c * 8) * 2) ^ ((row & 7) << 4)));
            *(uint4*)(Agen + off) = i0;
            *(uint4*)(Agen + 32768 + off) = i1;
        }
    }

    // ================= main tile loop (26 x 32-col tiles) =================
#pragma unroll 1
    for (int tl = 0; tl < 26; tl++) {
        if (tl < 25) {
            const char* src = (const char*)g_Bt + (size_t)(tl + 1) * 32768;
            unsigned dst = Bb[(tl + 1) & 1];
#pragma unroll
            for (int i = 0; i < 8; i++) {
                unsigned off = (unsigned)(i * 4096 + t * 16);
                asm volatile("cp.async.cg.shared.global [%0], [%1], 16;" :: "r"(dst + off), "l"(src + off) : "memory");
            }
            CP_COMMIT();
            CP_WAIT1();
        } else {
            CP_WAIT0();
        }
        __syncthreads();

        // dd[j*3 + term][4] for n8 halves j=0,1; terms a0b0, a1b0, a0b1
        float dd[6][4] = {};
        const unsigned Bt0 = Bb[tl & 1];
#pragma unroll 4
        for (int ks = 0; ks < 16; ks++) {
            unsigned kb = (unsigned)(ks << 5);
            unsigned aoff = abase_off + ((kb + achunk) ^ asw);
            unsigned boff = bbase_off + ((kb + bchunk) ^ bsw);
            unsigned a0[4], a1[4], b0[4], b1[4];
            ldsm4(a0, Abase + aoff);
            ldsm4(a1, Abase + 32768 + aoff);
            ldsm4(b0, Bt0 + boff);
            ldsm4(b1, Bt0 + 16384 + boff);
            mma16816h(dd[0], a0, b0);
            mma16816h(dd[1], a1, b0);
            mma16816h(dd[2], a0, b1);
            mma16816h(dd[3], a0, b0 + 2);
            mma16816h(dd[4], a1, b0 + 2);
            mma16816h(dd[5], a0, b1 + 2);
        }

        // ---- epilogue ----
        {
            int g = lane >> 2, tig = lane & 3;
            int gc = tile_gc(tl);
            float* dst; int dstride, dcol;
            if (tl < 8)       { dst = tbuf; dstride = 260; dcol = tl * 32; }
            else if (tl < 10) { dst = afb;  dstride = 66;  dcol = (tl - 8) * 32; }
            else if (tl < 18) { dst = tbuf; dstride = 260; dcol = (tl - 10) * 32; }
            else              { dst = tbuf; dstride = 260; dcol = (tl - 18) * 32; }
            int r0 = mrow0 + g, r1 = r0 + 8;
#pragma unroll
            for (int j = 0; j < 2; j++) {
                float e0 = dd[j*3][0] + dd[j*3+1][0] + dd[j*3+2][0];
                float e1 = dd[j*3][1] + dd[j*3+1][1] + dd[j*3+2][1];
                float e2 = dd[j*3][2] + dd[j*3+1][2] + dd[j*3+2][2];
                float e3 = dd[j*3][3] + dd[j*3+1][3] + dd[j*3+2][3];
                int lc = nh16 + j * 8 + 2 * tig;
                int colg = gc + lc;
                int dc = dcol + lc;
                if (tl < 18) {
                    float2 bb = *(const float2*)(g_bcat + colg);
                    float2 pi0 = *(const float2*)(g_P + (size_t)idxs[r0] * 576 + colg);
                    float2 pj0 = *(const float2*)(g_P + (size_t)NN * 576 + (size_t)idxs[64 + r0] * 576 + colg);
                    float2 pi1 = *(const float2*)(g_P + (size_t)idxs[r1] * 576 + colg);
                    float2 pj1 = *(const float2*)(g_P + (size_t)NN * 576 + (size_t)idxs[64 + r1] * 576 + colg);
                    *(float2*)(dst + (size_t)r0 * dstride + dc) =
                        make_float2(e0 + pi0.x + pj0.x + bb.x, e1 + pi0.y + pj0.y + bb.y);
                    *(float2*)(dst + (size_t)r1 * dstride + dc) =
                        make_float2(e2 + pi1.x + pj1.x + bb.x, e3 + pi1.y + pj1.y + bb.y);
                } else {
                    float2 bb = *(const float2*)(b2 + colg);
                    *(float2*)(dst + (size_t)r0 * dstride + dc) = make_float2(e0 + bb.x, e1 + bb.y);
                    *(float2*)(dst + (size_t)r1 * dstride + dc) = make_float2(e2 + bb.x, e3 + bb.y);
                }
            }
        }

        // ---- segment boundaries ----
        if (tl == 7) {
            __syncthreads();
            // LN new_if -> out
#pragma unroll 1
            for (int rr = 0; rr < 8; rr++) {
                int row = rr * 8 + wid;
                const float* trow = tbuf + row * 260;
                float v[8], s = 0.f, qq = 0.f;
#pragma unroll
                for (int j = 0; j < 8; j++) {
                    float xv = fmaxf(trow[lane + j * 32], 0.f);
                    v[j] = xv; s += xv; qq += xv * xv;
                }
                s = warp_sum(s); qq = warp_sum(qq);
                float mu = s * inv256, rstd = rsqrtf(qq * inv256 - mu * mu + EPS);
                float* o = out + 524288 + ((size_t)n * 64 + row) * 256;
#pragma unroll
                for (int j = 0; j < 8; j++) {
                    int c = lane + j * 32;
                    o[c] = (v[j] - mu) * rstd * gif[c] + beif[c];
                }
            }
        }
        if (tl == 17) {
            __syncthreads();
            // LN att (afb in place) + LN h1 (tbuf in place)
#pragma unroll 1
            for (int rr = 0; rr < 8; rr++) {
                int row = rr * 8 + wid;
                {
                    float* ar = afb + row * 66;
                    float x0 = fmaxf(ar[lane], 0.f), x1 = fmaxf(ar[32 + lane], 0.f);
                    float s = warp_sum(x0 + x1), qq = warp_sum(x0 * x0 + x1 * x1);
                    float mu = s * inv64, rstd = rsqrtf(qq * inv64 - mu * mu + EPS);
                    ar[lane] = (x0 - mu) * rstd * gatt[lane] + beatt[lane];
                    ar[32 + lane] = (x1 - mu) * rstd * gatt[32 + lane] + beatt[32 + lane];
                }
                {
                    float* trow = tbuf + row * 260;
                    float v[8], s = 0.f, qq = 0.f;
#pragma unroll
                    for (int j = 0; j < 8; j++) {
                        float xv = fmaxf(trow[lane + j * 32], 0.f);
                        v[j] = xv; s += xv; qq += xv * xv;
                    }
                    s = warp_sum(s); qq = warp_sum(qq);
                    float mu = s * inv256, rstd = rsqrtf(qq * inv256 - mu * mu + EPS);
#pragma unroll
                    for (int j = 0; j < 8; j++) {
                        int c = lane + j * 32;
                        trow[c] = (v[j] - mu) * rstd * g1[c] + be1[c];
                    }
                }
            }
            __syncthreads();
            // rewrite A = h1 (2 fp16 images)
            {
                int row = t >> 2, k0 = (t & 3) * 64;
                const float* src = tbuf + row * 260 + k0;
#pragma unroll
                for (int c = 0; c < 8; c++) {
                    float4 v0 = *(const float4*)(src + c * 8);
                    float4 v1 = *(const float4*)(src + c * 8 + 4);
                    uint4 i0, i1;
                    split2h(v0.x, v0.y, i0.x, i1.x);
                    split2h(v0.z, v0.w, i0.y, i1.y);
                    split2h(v1.x, v1.y, i0.z, i1.z);
                    split2h(v1.z, v1.w, i0.w, i1.w);
                    unsigned off = (unsigned)(row * 512 + (((k0 + c * 8) * 2) ^ ((row & 7) << 4)));
                    *(uint4*)(Agen + off) = i0;
                    *(uint4*)(Agen + 32768 + off) = i1;
                }
            }
        }
        __syncthreads();   // guard B-buffer rotate + A visibility
    }

    // ---- Phase 4: h2 = LN(relu(t2)); logits -> slog ----
#pragma unroll 1
    for (int rr = 0; rr < 8; rr++) {
        int row = rr * 8 + wid;
        const float* trow = tbuf + row * 260;
        float v[8], s = 0.f, qq = 0.f;
#pragma unroll
        for (int j = 0; j < 8; j++) {
            float xv = fmaxf(trow[lane + j * 32], 0.f);
            v[j] = xv; s += xv; qq += xv * xv;
        }
        s = warp_sum(s); qq = warp_sum(qq);
        float mu = s * inv256, rstd = rsqrtf(qq * inv256 - mu * mu + EPS);
        float l0 = 0.f, l1 = 0.f, l2 = 0.f, l3 = 0.f;
#pragma unroll
        for (int j = 0; j < 8; j++) {
            int c = lane + j * 32;
            float y = (v[j] - mu) * rstd * g2[c] + be2[c];
            float4 wp = *(const float4*)(wpre + (size_t)c * 4);
            l0 += y * wp.x; l1 += y * wp.y; l2 += y * wp.z; l3 += y * wp.w;
        }
        l0 = warp_sum(l0); l1 = warp_sum(l1); l2 = warp_sum(l2); l3 = warp_sum(l3);
        if (lane == 0) {
            bool mk = mask[n * 64 + row] != 0;
            slog[row * 4 + 0] = mk ? NEG : (l0 + bpre[0]);
            slog[row * 4 + 1] = mk ? NEG : (l1 + bpre[1]);
            slog[row * 4 + 2] = mk ? NEG : (l2 + bpre[2]);
            slog[row * 4 + 3] = mk ? NEG : (l3 + bpre[3]);
        }
    }
    __syncthreads();

    // ---- Phase 5: per-head top-16 softmax ----
    if (wid < 4) {
        int h = wid;
        float v0 = slog[lane * 4 + h], v1 = slog[(32 + lane) * 4 + h];
        float c0 = v0, c1 = v1;
        float thr = NEG, maxv = NEG;
#pragma unroll 1
        for (int it = 0; it < 16; it++) {
            float loc = fmaxf(c0, c1);
            float m = warp_max(loc);
            if (it == 0) maxv = m;
            if (m == NEG) break;
            thr = m;
            unsigned bl = __ballot_sync(0xffffffffu, loc == m);
            int src = __ffs(bl) - 1;
            if (lane == src) { if (c0 == m) c0 = NEG; else c1 = NEG; }
        }
        float e0 = (v0 >= thr) ? expf(v0 - maxv) : 0.f;
        float e1 = (v1 >= thr) ? expf(v1 - maxv) : 0.f;
        float inv = 1.f / warp_sum(e0 + e1);
        wsm[h * 64 + lane] = e0 * inv;
        wsm[h * 64 + 32 + lane] = e1 * inv;
    }
    __syncthreads();

    // ---- Phase 6: agg[d,h] = sum_m w[h,m] * af[m,d] ----
    {
        int d = t >> 2, h = t & 3;
        float s = 0.f;
#pragma unroll
        for (int m = 0; m < 64; m++) s += wsm[h * 64 + m] * afb[m * 66 + d];
        aggs[t] = s;
    }
    __syncthreads();

    // ---- Phase 7: x_out = LN(relu(agg @ wg + bg)) ----
    {
        float v0a = 0.f, v1a = 0.f, v2a = 0.f, v3a = 0.f;
#pragma unroll 4
        for (int k = 0; k < 256; k += 4) {
            v0a += aggs[k]     * wg[(size_t)k * 256 + t];
            v1a += aggs[k + 1] * wg[(size_t)(k + 1) * 256 + t];
            v2a += aggs[k + 2] * wg[(size_t)(k + 2) * 256 + t];
            v3a += aggs[k + 3] * wg[(size_t)(k + 3) * 256 + t];
        }
        float v = fmaxf((v0a + v1a) + (v2a + v3a) + bg[t], 0.f);
        float s = warp_sum(v), qq = warp_sum(v * v);
        if (lane == 0) { red[wid] = s; red[8 + wid] = qq; }
        __syncthreads();
        if (t < 32) {
            float a = (lane < 8) ? red[lane] : 0.f;
            float b = (lane < 8) ? red[8 + lane] : 0.f;
#pragma unroll
            for (int o = 4; o; o >>= 1) {
                a += __shfl_xor_sync(0xffffffffu, a, o);
                b += __shfl_xor_sync(0xffffffffu, b, o);
            }
            if (lane == 0) { red[0] = a; red[8] = b; }
        }
        __syncthreads();
        float mu = red[0] * inv256, rstd = rsqrtf(red[8] * inv256 - mu * mu + EPS);
        float y = (v - mu) * rstd * gg[t] + beg[t];
        out[(size_t)n * 256 + t] = y;
        out[34078720ull + (size_t)n * 256 + t] = y;
    }
}

// ---------------- launch ----------------
extern "C" void kernel_launch(void* const* d_in, const int* in_sizes, int n_in,
                              void* d_out, int out_size) {
    const float* x = (const float*)d_in[0];
    const float* iff = (const float*)d_in[1];
    const int* mask = (const int*)d_in[2];
    const int* ai = (const int*)d_in[3];
    const int* aj = (const int*)d_in[4];
    const float* w1 = (const float*)d_in[5], *b1 = (const float*)d_in[6];
    const float* g1 = (const float*)d_in[7], *be1 = (const float*)d_in[8];
    const float* w2 = (const float*)d_in[9], *b2 = (const float*)d_in[10];
    const float* g2 = (const float*)d_in[11], *be2 = (const float*)d_in[12];
    const float* wpre = (const float*)d_in[13], *bpre = (const float*)d_in[14];
    const float* watt = (const float*)d_in[15], *batt = (const float*)d_in[16];
    const float* gatt = (const float*)d_in[17], *beatt = (const float*)d_in[18];
    const float* wif = (const float*)d_in[19], *bif = (const float*)d_in[20];
    const float* gif = (const float*)d_in[21], *beif = (const float*)d_in[22];
    const float* wg = (const float*)d_in[23], *bg = (const float*)d_in[24];
    const float* gg = (const float*)d_in[25], *beg = (const float*)d_in[26];
    float* out = (float*)d_out;

    const int PS = (256 * 65 + 32 * 65) * 4;
    const int BS = 215552;
    cudaFuncSetAttribute(p_kernel, cudaFuncAttributeMaxDynamicSharedMemorySize, PS);
    cudaFuncSetAttribute(big_kernel, cudaFuncAttributeMaxDynamicSharedMemorySize, BS);

    pack_kernel<<<1152, 256>>>(w1, watt, wif, b1, batt, bif, w2);
    p_kernel<<<dim3(32, 2, 3), 256, PS>>>(x);
    big_kernel<<<2048, 256, BS>>>(iff, ai, aj, g1, be1, gatt, beatt, gif, beif,
                                  b2, g2, be2, wpre, bpre, mask,
                                  wg, bg, gg, beg, out);
}

// round 11
// speedup vs baseline: 1.6442x; 1.0466x over previous
#include <cuda_runtime.h>
#include <cuda_fp16.h>
#include <cstdint>
#include <cstddef>

#define NN 2048
#define EPS 1e-5f

// ---------------- device scratch ----------------
__device__ float g_Wcat[512 * 576];                 // x_i|x_j weight rows, packed cols
__device__ float g_bcat[576];                       // packed biases
__device__ float g_P[2 * NN * 576];                 // Pi, Pj tables
// 26 tiles x 2 images x (32 n x 256 k) fp16 = 26 x 16384 elems
__device__ __align__(16) __half g_Bt[26 * 16384];

__device__ __forceinline__ float warp_sum(float v) {
#pragma unroll
    for (int o = 16; o; o >>= 1) v += __shfl_xor_sync(0xffffffffu, v, o);
    return v;
}
__device__ __forceinline__ float warp_max(float v) {
#pragma unroll
    for (int o = 16; o; o >>= 1) v = fmaxf(v, __shfl_xor_sync(0xffffffffu, v, o));
    return v;
}

#define CP_COMMIT() asm volatile("cp.async.commit_group;" ::: "memory")
#define CP_WAIT1()  asm volatile("cp.async.wait_group 1;" ::: "memory")
#define CP_WAIT0()  asm volatile("cp.async.wait_group 0;" ::: "memory")

__device__ __forceinline__ void ldsm4(unsigned r[4], unsigned addr) {
    asm volatile("ldmatrix.sync.aligned.m8n8.x4.shared.b16 {%0,%1,%2,%3}, [%4];"
                 : "=r"(r[0]), "=r"(r[1]), "=r"(r[2]), "=r"(r[3]) : "r"(addr));
}
__device__ __forceinline__ void mma16816h(float d[4], const unsigned a[4], const unsigned b[2]) {
    asm volatile("mma.sync.aligned.m16n8k16.row.col.f32.f16.f16.f32 "
                 "{%0,%1,%2,%3}, {%4,%5,%6,%7}, {%8,%9}, {%0,%1,%2,%3};"
                 : "+f"(d[0]), "+f"(d[1]), "+f"(d[2]), "+f"(d[3])
                 : "r"(a[0]), "r"(a[1]), "r"(a[2]), "r"(a[3]), "r"(b[0]), "r"(b[1]));
}

// 2-way fp16 split of an fp32 pair -> two packed half2 words (hi image, residual image)
__device__ __forceinline__ void split2h(float a, float b, uint32_t& w0, uint32_t& w1) {
    __half a0 = __float2half_rn(a), b0 = __float2half_rn(b);
    __half a1 = __float2half_rn(a - __half2float(a0));
    __half b1 = __float2half_rn(b - __half2float(b0));
    w0 = ((uint32_t)__half_as_ushort(b0) << 16) | (uint32_t)__half_as_ushort(a0);
    w1 = ((uint32_t)__half_as_ushort(b1) << 16) | (uint32_t)__half_as_ushort(a1);
}

// 32-col tiles: 0-7 new_if(gc 320..575), 8-9 att(gc 256..319), 10-17 h1(gc 0..255), 18-25 w2
__device__ __host__ __forceinline__ int tile_gc(int tl) {
    return (tl < 8) ? 320 + tl * 32 : (tl < 10) ? 256 + (tl - 8) * 32
          : (tl < 18) ? (tl - 10) * 32 : (tl - 18) * 32;
}

// ---------------- K0: pack ----------------
__global__ void pack_kernel(const float* __restrict__ w1, const float* __restrict__ watt,
                            const float* __restrict__ wif, const float* __restrict__ b1,
                            const float* __restrict__ batt, const float* __restrict__ bif,
                            const float* __restrict__ w2) {
    int idx = blockIdx.x * blockDim.x + threadIdx.x;
    if (idx < 512 * 576) {
        int r = idx / 576, c = idx - r * 576;
        g_Wcat[idx] = (c < 256) ? w1[r * 256 + c]
                     : (c < 320) ? watt[r * 64 + (c - 256)]
                                 : wif[r * 256 + (c - 320)];
    }
    if (idx < 576)
        g_bcat[idx] = (idx < 256) ? b1[idx] : (idx < 320) ? batt[idx - 256] : bif[idx - 320];
    if (idx < 26 * 8192) {
        int tl = idx >> 13, rr = idx & 8191;
        int n = rr >> 8, k = rr & 255;   // n in 0..31, k in 0..255
        float w;
        if (tl < 18) {
            int c = tile_gc(tl) + n, r = 512 + k;
            w = (c < 256) ? w1[r * 256 + c]
               : (c < 320) ? watt[r * 64 + (c - 256)]
                           : wif[r * 256 + (c - 320)];
        } else {
            w = w2[k * 256 + (tl - 18) * 32 + n];
        }
        __half v0 = __float2half_rn(w);
        __half v1 = __float2half_rn(w - __half2float(v0));
        int byte = n * 512 + ((k * 2) ^ ((n & 7) << 4));   // 16B-chunk XOR swizzle
        size_t base = (size_t)tl * 16384 + (byte >> 1);
        g_Bt[base] = v0;
        g_Bt[base + 8192] = v1;
    }
}

// ---------------- K1: P = x @ Wcat(part) ----------------
__device__ __forceinline__ void micro_fma32(const float* __restrict__ ap,
                                            const float* __restrict__ bp, float acc[4][4]) {
#pragma unroll 8
    for (int k = 0; k < 32; k++) {
        const float* apk = ap + k * 65;
        const float* bpk = bp + k * 65;
        float a0 = apk[0], a1 = apk[1], a2 = apk[2], a3 = apk[3];
        float b0 = bpk[0], b1 = bpk[1], b2 = bpk[2], b3 = bpk[3];
        acc[0][0] += a0*b0; acc[0][1] += a0*b1; acc[0][2] += a0*b2; acc[0][3] += a0*b3;
        acc[1][0] += a1*b0; acc[1][1] += a1*b1; acc[1][2] += a1*b2; acc[1][3] += a1*b3;
        acc[2][0] += a2*b0; acc[2][1] += a2*b1; acc[2][2] += a2*b2; acc[2][3] += a2*b3;
        acc[3][0] += a3*b0; acc[3][1] += a3*b1; acc[3][2] += a3*b2; acc[3][3] += a3*b3;
    }
}
__global__ void __launch_bounds__(256) p_kernel(const float* __restrict__ x) {
    extern __shared__ float sm[];
    float* xs = sm;
    float* wsh = xs + 256 * 65;
    int nb = blockIdx.x, part = blockIdx.y, cg = blockIdx.z;
    int t = threadIdx.x, ty = t >> 4, tx = t & 15;
    {
        int row = t >> 2, k0 = (t & 3) * 64;
        const float* src = x + (size_t)(nb * 64 + row) * 256 + k0;
#pragma unroll
        for (int k = 0; k < 64; k += 4) {
            float4 v = *(const float4*)(src + k);
            xs[(k0+k)*65+row]=v.x; xs[(k0+k+1)*65+row]=v.y;
            xs[(k0+k+2)*65+row]=v.z; xs[(k0+k+3)*65+row]=v.w;
        }
    }
    __syncthreads();
    for (int cc = cg * 3; cc < cg * 3 + 3; cc++) {
        float acc[4][4] = {};
        for (int kp = 0; kp < 8; kp++) {
            {
                int k = t >> 3, cb = (t & 7) * 8;
                const float* src = g_Wcat + (size_t)(part*256 + kp*32 + k)*576 + cc*64 + cb;
                float4 v0 = *(const float4*)src, v1 = *(const float4*)(src + 4);
                float* d = wsh + k*65 + cb;
                d[0]=v0.x; d[1]=v0.y; d[2]=v0.z; d[3]=v0.w;
                d[4]=v1.x; d[5]=v1.y; d[6]=v1.z; d[7]=v1.w;
            }
            __syncthreads();
            micro_fma32(xs + kp*32*65 + ty*4, wsh + tx*4, acc);
            __syncthreads();
        }
#pragma unroll
        for (int ri = 0; ri < 4; ri++) {
            float4 v = make_float4(acc[ri][0], acc[ri][1], acc[ri][2], acc[ri][3]);
            *(float4*)(g_P + (size_t)part*NN*576 + (size_t)(nb*64 + ty*4 + ri)*576 + cc*64 + tx*4) = v;
        }
    }
}

// ---------------- K2: fused per-site kernel ----------------
// smem (bytes): [16..528) idxs; A imgs at 1024 / 33792 (32KB each);
// B dbl buf 66560 / 99328 (32768 each); tbuf 132096 [64][260] fp32; afb 198656 [64][66].
__global__ void __launch_bounds__(256) big_kernel(
    const float* __restrict__ IF, const int* __restrict__ ai, const int* __restrict__ aj,
    const float* __restrict__ g1, const float* __restrict__ be1,
    const float* __restrict__ gatt, const float* __restrict__ beatt,
    const float* __restrict__ gif, const float* __restrict__ beif,
    const float* __restrict__ b2, const float* __restrict__ g2, const float* __restrict__ be2,
    const float* __restrict__ wpre, const float* __restrict__ bpre,
    const int* __restrict__ mask,
    const float* __restrict__ wg, const float* __restrict__ bg,
    const float* __restrict__ gg, const float* __restrict__ beg,
    float* __restrict__ out) {
    extern __shared__ char smem[];
    const unsigned sb = (unsigned)__cvta_generic_to_shared(smem);
    int* idxs = (int*)(smem + 16);
    char* Agen = smem + 1024;
    const unsigned Abase = sb + 1024;
    const unsigned Bb[2] = { sb + 66560, sb + 99328 };
    float* tbuf = (float*)(smem + 132096);   // [64][260]
    float* afb  = (float*)(smem + 198656);   // [64][66]
    float* slog = (float*)(smem + 66560);    // aliases, used after GEMMs
    float* wsm  = (float*)(smem + 67584);
    float* aggs = (float*)(smem + 68608);
    float* red  = (float*)(smem + 69632);

    const int n = blockIdx.x, t = threadIdx.x;
    const int lane = t & 31, wid = t >> 5;
    const int mrow0 = (wid >> 1) << 4;       // M16 group (4 groups across warp pairs)
    const int nh16 = (wid & 1) << 4;         // N16 half within 32-col tile
    const float NEG = __int_as_float(0xff800000);
    const float inv256 = 1.f / 256.f, inv64 = 1.f / 64.f;

    // ldmatrix geometry: A fragment (m16k16)
    const int arow = mrow0 + (lane & 15);
    const unsigned abase_off = (unsigned)(arow * 512);
    const unsigned asw = (unsigned)((arow & 7) << 4);
    const unsigned achunk = (unsigned)((lane >> 4) << 4);
    // B fragment (n16k16)
    const int brow = nh16 + ((lane >> 4) << 3) + (lane & 7);
    const unsigned bbase_off = (unsigned)(brow * 512);
    const unsigned bsw = (unsigned)((brow & 7) << 4);
    const unsigned bchunk = (unsigned)(((lane >> 3) & 1) << 4);
    // epilogue geometry (lane-constant)
    const int eg = lane >> 2, etig = lane & 3;
    const int er0 = mrow0 + eg, er1 = mrow0 + eg + 8;

    if (t < 64) { idxs[t] = ai[n * 64 + t]; idxs[64 + t] = aj[n * 64 + t]; }

    // prefetch B tile 0 (2-term tile: hi image only, 16KB)
    {
        const char* src = (const char*)g_Bt;
#pragma unroll
        for (int i = 0; i < 4; i++) {
            unsigned off = (unsigned)(i * 4096 + t * 16);
            asm volatile("cp.async.cg.shared.global [%0], [%1], 16;" :: "r"(Bb[0] + off), "l"(src + off) : "memory");
        }
        CP_COMMIT();
    }

    // convert IF -> A (2 fp16 images, swizzled)
    {
        int row = t >> 2, k0 = (t & 3) * 64;
        const float* src = IF + (size_t)(n * 64 + row) * 256 + k0;
#pragma unroll
        for (int c = 0; c < 8; c++) {
            float4 v0 = *(const float4*)(src + c * 8);
            float4 v1 = *(const float4*)(src + c * 8 + 4);
            uint4 i0, i1;
            split2h(v0.x, v0.y, i0.x, i1.x);
            split2h(v0.z, v0.w, i0.y, i1.y);
            split2h(v1.x, v1.y, i0.z, i1.z);
            split2h(v1.z, v1.w, i0.w, i1.w);
            unsigned off = (unsigned)(row * 512 + (((k0 + c * 8) * 2) ^ ((row & 7) << 4)));
            *(uint4*)(Agen + off) = i0;
            *(uint4*)(Agen + 32768 + off) = i1;
        }
    }

    // ================= main tile loop (26 x 32-col tiles) =================
#pragma unroll 1
    for (int tl = 0; tl < 26; tl++) {
        if (tl < 25) {
            const char* src = (const char*)g_Bt + (size_t)(tl + 1) * 32768;
            unsigned dst = Bb[(tl + 1) & 1];
            int nch = (tl + 1 < 10) ? 4 : 8;   // 2-term tiles: hi image only
#pragma unroll 1
            for (int i = 0; i < nch; i++) {
                unsigned off = (unsigned)(i * 4096 + t * 16);
                asm volatile("cp.async.cg.shared.global [%0], [%1], 16;" :: "r"(dst + off), "l"(src + off) : "memory");
            }
            CP_COMMIT();
            CP_WAIT1();
        } else {
            CP_WAIT0();
        }
        __syncthreads();

        // ---- register-prefetch epilogue operands (hidden under mma loop) ----
        float2 p_pi0[2], p_pj0[2], p_pi1[2], p_pj1[2], p_bb[2];
        {
            int gc_e = tile_gc(tl);
            if (tl < 18) {
#pragma unroll
                for (int j = 0; j < 2; j++) {
                    int colg = gc_e + nh16 + j * 8 + 2 * etig;
                    p_bb[j]  = *(const float2*)(g_bcat + colg);
                    p_pi0[j] = *(const float2*)(g_P + (size_t)idxs[er0] * 576 + colg);
                    p_pj0[j] = *(const float2*)(g_P + (size_t)NN * 576 + (size_t)idxs[64 + er0] * 576 + colg);
                    p_pi1[j] = *(const float2*)(g_P + (size_t)idxs[er1] * 576 + colg);
                    p_pj1[j] = *(const float2*)(g_P + (size_t)NN * 576 + (size_t)idxs[64 + er1] * 576 + colg);
                }
            } else {
#pragma unroll
                for (int j = 0; j < 2; j++) {
                    int colg = gc_e + nh16 + j * 8 + 2 * etig;
                    p_bb[j]  = *(const float2*)(b2 + colg);
                    p_pi0[j] = p_pj0[j] = p_pi1[j] = p_pj1[j] = make_float2(0.f, 0.f);
                }
            }
        }

        // dd[j*3 + term][4] for n8 halves j=0,1; terms a0b0, a1b0, a0b1
        const bool full = (tl >= 10);   // selection chain: 3-term; new_if/att: 2-term
        float dd[6][4] = {};
        const unsigned Bt0 = Bb[tl & 1];
#pragma unroll 4
        for (int ks = 0; ks < 16; ks++) {
            unsigned kb = (unsigned)(ks << 5);
            unsigned aoff = abase_off + ((kb + achunk) ^ asw);
            unsigned boff = bbase_off + ((kb + bchunk) ^ bsw);
            unsigned a0[4], a1[4], b0[4];
            ldsm4(a0, Abase + aoff);
            ldsm4(a1, Abase + 32768 + aoff);
            ldsm4(b0, Bt0 + boff);
            mma16816h(dd[0], a0, b0);
            mma16816h(dd[1], a1, b0);
            mma16816h(dd[3], a0, b0 + 2);
            mma16816h(dd[4], a1, b0 + 2);
            if (full) {
                unsigned b1[4];
                ldsm4(b1, Bt0 + 16384 + boff);
                mma16816h(dd[2], a0, b1);
                mma16816h(dd[5], a0, b1 + 2);
            }
        }

        // ---- epilogue (uniform adds; p_* are zero for w2 tiles) ----
        {
            float* dst; int dstride, dcol;
            if (tl < 8)       { dst = tbuf; dstride = 260; dcol = tl * 32; }
            else if (tl < 10) { dst = afb;  dstride = 66;  dcol = (tl - 8) * 32; }
            else if (tl < 18) { dst = tbuf; dstride = 260; dcol = (tl - 10) * 32; }
            else              { dst = tbuf; dstride = 260; dcol = (tl - 18) * 32; }
#pragma unroll
            for (int j = 0; j < 2; j++) {
                float e0 = dd[j*3][0] + dd[j*3+1][0] + dd[j*3+2][0];
                float e1 = dd[j*3][1] + dd[j*3+1][1] + dd[j*3+2][1];
                float e2 = dd[j*3][2] + dd[j*3+1][2] + dd[j*3+2][2];
                float e3 = dd[j*3][3] + dd[j*3+1][3] + dd[j*3+2][3];
                int dc = dcol + nh16 + j * 8 + 2 * etig;
                *(float2*)(dst + (size_t)er0 * dstride + dc) =
                    make_float2(e0 + p_pi0[j].x + p_pj0[j].x + p_bb[j].x,
                                e1 + p_pi0[j].y + p_pj0[j].y + p_bb[j].y);
                *(float2*)(dst + (size_t)er1 * dstride + dc) =
                    make_float2(e2 + p_pi1[j].x + p_pj1[j].x + p_bb[j].x,
                                e3 + p_pi1[j].y + p_pj1[j].y + p_bb[j].y);
            }
        }

        // ---- segment boundaries ----
        if (tl == 7) {
            __syncthreads();
            // LN new_if -> out
#pragma unroll 1
            for (int rr = 0; rr < 8; rr++) {
                int row = rr * 8 + wid;
                const float* trow = tbuf + row * 260;
                float v[8], s = 0.f, qq = 0.f;
#pragma unroll
                for (int j = 0; j < 8; j++) {
                    float xv = fmaxf(trow[lane + j * 32], 0.f);
                    v[j] = xv; s += xv; qq += xv * xv;
                }
                s = warp_sum(s); qq = warp_sum(qq);
                float mu = s * inv256, rstd = rsqrtf(qq * inv256 - mu * mu + EPS);
                float* o = out + 524288 + ((size_t)n * 64 + row) * 256;
#pragma unroll
                for (int j = 0; j < 8; j++) {
                    int c = lane + j * 32;
                    o[c] = (v[j] - mu) * rstd * gif[c] + beif[c];
                }
            }
        }
        if (tl == 17) {
            __syncthreads();
            // LN att (afb in place) + LN h1 (tbuf in place)
#pragma unroll 1
            for (int rr = 0; rr < 8; rr++) {
                int row = rr * 8 + wid;
                {
                    float* ar = afb + row * 66;
                    float x0 = fmaxf(ar[lane], 0.f), x1 = fmaxf(ar[32 + lane], 0.f);
                    float s = warp_sum(x0 + x1), qq = warp_sum(x0 * x0 + x1 * x1);
                    float mu = s * inv64, rstd = rsqrtf(qq * inv64 - mu * mu + EPS);
                    ar[lane] = (x0 - mu) * rstd * gatt[lane] + beatt[lane];
                    ar[32 + lane] = (x1 - mu) * rstd * gatt[32 + lane] + beatt[32 + lane];
                }
                {
                    float* trow = tbuf + row * 260;
                    float v[8], s = 0.f, qq = 0.f;
#pragma unroll
                    for (int j = 0; j < 8; j++) {
                        float xv = fmaxf(trow[lane + j * 32], 0.f);
                        v[j] = xv; s += xv; qq += xv * xv;
                    }
                    s = warp_sum(s); qq = warp_sum(qq);
                    float mu = s * inv256, rstd = rsqrtf(qq * inv256 - mu * mu + EPS);
#pragma unroll
                    for (int j = 0; j < 8; j++) {
                        int c = lane + j * 32;
                        trow[c] = (v[j] - mu) * rstd * g1[c] + be1[c];
                    }
                }
            }
            __syncthreads();
            // rewrite A = h1 (2 fp16 images)
            {
                int row = t >> 2, k0 = (t & 3) * 64;
                const float* src = tbuf + row * 260 + k0;
#pragma unroll
                for (int c = 0; c < 8; c++) {
                    float4 v0 = *(const float4*)(src + c * 8);
                    float4 v1 = *(const float4*)(src + c * 8 + 4);
                    uint4 i0, i1;
                    split2h(v0.x, v0.y, i0.x, i1.x);
                    split2h(v0.z, v0.w, i0.y, i1.y);
                    split2h(v1.x, v1.y, i0.z, i1.z);
                    split2h(v1.z, v1.w, i0.w, i1.w);
                    unsigned off = (unsigned)(row * 512 + (((k0 + c * 8) * 2) ^ ((row & 7) << 4)));
                    *(uint4*)(Agen + off) = i0;
                    *(uint4*)(Agen + 32768 + off) = i1;
                }
            }
        }
        __syncthreads();   // guard B-buffer rotate + A visibility
    }

    // ---- Phase 4: h2 = LN(relu(t2)); logits -> slog ----
#pragma unroll 1
    for (int rr = 0; rr < 8; rr++) {
        int row = rr * 8 + wid;
        const float* trow = tbuf + row * 260;
        float v[8], s = 0.f, qq = 0.f;
#pragma unroll
        for (int j = 0; j < 8; j++) {
            float xv = fmaxf(trow[lane + j * 32], 0.f);
            v[j] = xv; s += xv; qq += xv * xv;
        }
        s = warp_sum(s); qq = warp_sum(qq);
        float mu = s * inv256, rstd = rsqrtf(qq * inv256 - mu * mu + EPS);
        float l0 = 0.f, l1 = 0.f, l2 = 0.f, l3 = 0.f;
#pragma unroll
        for (int j = 0; j < 8; j++) {
            int c = lane + j * 32;
            float y = (v[j] - mu) * rstd * g2[c] + be2[c];
            float4 wp = *(const float4*)(wpre + (size_t)c * 4);
            l0 += y * wp.x; l1 += y * wp.y; l2 += y * wp.z; l3 += y * wp.w;
        }
        l0 = warp_sum(l0); l1 = warp_sum(l1); l2 = warp_sum(l2); l3 = warp_sum(l3);
        if (lane == 0) {
            bool mk = mask[n * 64 + row] != 0;
            slog[row * 4 + 0] = mk ? NEG : (l0 + bpre[0]);
            slog[row * 4 + 1] = mk ? NEG : (l1 + bpre[1]);
            slog[row * 4 + 2] = mk ? NEG : (l2 + bpre[2]);
            slog[row * 4 + 3] = mk ? NEG : (l3 + bpre[3]);
        }
    }
    __syncthreads();

    // ---- Phase 5: per-head top-16 softmax ----
    if (wid < 4) {
        int h = wid;
        float v0 = slog[lane * 4 + h], v1 = slog[(32 + lane) * 4 + h];
        float c0 = v0, c1 = v1;
        float thr = NEG, maxv = NEG;
#pragma unroll 1
        for (int it = 0; it < 16; it++) {
            float loc = fmaxf(c0, c1);
            float m = warp_max(loc);
            if (it == 0) maxv = m;
            if (m == NEG) break;
            thr = m;
            unsigned bl = __ballot_sync(0xffffffffu, loc == m);
            int src = __ffs(bl) - 1;
            if (lane == src) { if (c0 == m) c0 = NEG; else c1 = NEG; }
        }
        float e0 = (v0 >= thr) ? expf(v0 - maxv) : 0.f;
        float e1 = (v1 >= thr) ? expf(v1 - maxv) : 0.f;
        float inv = 1.f / warp_sum(e0 + e1);
        wsm[h * 64 + lane] = e0 * inv;
        wsm[h * 64 + 32 + lane] = e1 * inv;
    }
    __syncthreads();

    // ---- Phase 6: agg[d,h] = sum_m w[h,m] * af[m,d] ----
    {
        int d = t >> 2, h = t & 3;
        float s = 0.f;
#pragma unroll
        for (int m = 0; m < 64; m++) s += wsm[h * 64 + m] * afb[m * 66 + d];
        aggs[t] = s;
    }
    __syncthreads();

    // ---- Phase 7: x_out = LN(relu(agg @ wg + bg)) ----
    {
        float v0a = 0.f, v1a = 0.f, v2a = 0.f, v3a = 0.f;
#pragma unroll 4
        for (int k = 0; k < 256; k += 4) {
            v0a += aggs[k]     * wg[(size_t)k * 256 + t];
            v1a += aggs[k + 1] * wg[(size_t)(k + 1) * 256 + t];
            v2a += aggs[k + 2] * wg[(size_t)(k + 2) * 256 + t];
            v3a += aggs[k + 3] * wg[(size_t)(k + 3) * 256 + t];
        }
        float v = fmaxf((v0a + v1a) + (v2a + v3a) + bg[t], 0.f);
        float s = warp_sum(v), qq = warp_sum(v * v);
        if (lane == 0) { red[wid] = s; red[8 + wid] = qq; }
        __syncthreads();
        if (t < 32) {
            float a = (lane < 8) ? red[lane] : 0.f;
            float b = (lane < 8) ? red[8 + lane] : 0.f;
#pragma unroll
            for (int o = 4; o; o >>= 1) {
                a += __shfl_xor_sync(0xffffffffu, a, o);
                b += __shfl_xor_sync(0xffffffffu, b, o);
            }
            if (lane == 0) { red[0] = a; red[8] = b; }
        }
        __syncthreads();
        float mu = red[0] * inv256, rstd = rsqrtf(red[8] * inv256 - mu * mu + EPS);
        float y = (v - mu) * rstd * gg[t] + beg[t];
        out[(size_t)n * 256 + t] = y;
        out[34078720ull + (size_t)n * 256 + t] = y;
    }
}

// ---------------- launch ----------------
extern "C" void kernel_launch(void* const* d_in, const int* in_sizes, int n_in,
                              void* d_out, int out_size) {
    const float* x = (const float*)d_in[0];
    const float* iff = (const float*)d_in[1];
    const int* mask = (const int*)d_in[2];
    const int* ai = (const int*)d_in[3];
    const int* aj = (const int*)d_in[4];
    const float* w1 = (const float*)d_in[5], *b1 = (const float*)d_in[6];
    const float* g1 = (const float*)d_in[7], *be1 = (const float*)d_in[8];
    const float* w2 = (const float*)d_in[9], *b2 = (const float*)d_in[10];
    const float* g2 = (const float*)d_in[11], *be2 = (const float*)d_in[12];
    const float* wpre = (const float*)d_in[13], *bpre = (const float*)d_in[14];
    const float* watt = (const float*)d_in[15], *batt = (const float*)d_in[16];
    const float* gatt = (const float*)d_in[17], *beatt = (const float*)d_in[18];
    const float* wif = (const float*)d_in[19], *bif = (const float*)d_in[20];
    const float* gif = (const float*)d_in[21], *beif = (const float*)d_in[22];
    const float* wg = (const float*)d_in[23], *bg = (const float*)d_in[24];
    const float* gg = (const float*)d_in[25], *beg = (const float*)d_in[26];
    float* out = (float*)d_out;

    const int PS = (256 * 65 + 32 * 65) * 4;
    const int BS = 215552;
    cudaFuncSetAttribute(p_kernel, cudaFuncAttributeMaxDynamicSharedMemorySize, PS);
    cudaFuncSetAttribute(big_kernel, cudaFuncAttributeMaxDynamicSharedMemorySize, BS);

    pack_kernel<<<1152, 256>>>(w1, watt, wif, b1, batt, bif, w2);
    p_kernel<<<dim3(32, 2, 3), 256, PS>>>(x);
    big_kernel<<<2048, 256, BS>>>(iff, ai, aj, g1, be1, gatt, beatt, gif, beif,
                                  b2, g2, be2, wpre, bpre, mask,
                                  wg, bg, gg, beg, out);
}

// round 12
// speedup vs baseline: 1.6793x; 1.0213x over previous
#include <cuda_runtime.h>
#include <cuda_fp16.h>
#include <cstdint>
#include <cstddef>

#define NN 2048
#define EPS 1e-5f

// ---------------- device scratch ----------------
__device__ float g_Wcat[512 * 576];                 // x_i|x_j weight rows, packed cols
__device__ float g_bcat[576];                       // packed biases
__device__ float g_P[2 * NN * 576];                 // Pi, Pj tables
// 26 tiles x 2 images x (32 n x 256 k) fp16 = 26 x 16384 elems
__device__ __align__(16) __half g_Bt[26 * 16384];

__device__ __forceinline__ float warp_sum(float v) {
#pragma unroll
    for (int o = 16; o; o >>= 1) v += __shfl_xor_sync(0xffffffffu, v, o);
    return v;
}
__device__ __forceinline__ float warp_max(float v) {
#pragma unroll
    for (int o = 16; o; o >>= 1) v = fmaxf(v, __shfl_xor_sync(0xffffffffu, v, o));
    return v;
}

#define CP_COMMIT() asm volatile("cp.async.commit_group;" ::: "memory")
#define CP_WAIT0()  asm volatile("cp.async.wait_group 0;" ::: "memory")

__device__ __forceinline__ void ldsm4(unsigned r[4], unsigned addr) {
    asm volatile("ldmatrix.sync.aligned.m8n8.x4.shared.b16 {%0,%1,%2,%3}, [%4];"
                 : "=r"(r[0]), "=r"(r[1]), "=r"(r[2]), "=r"(r[3]) : "r"(addr));
}
__device__ __forceinline__ void mma16816h(float d[4], const unsigned a[4], const unsigned b[2]) {
    asm volatile("mma.sync.aligned.m16n8k16.row.col.f32.f16.f16.f32 "
                 "{%0,%1,%2,%3}, {%4,%5,%6,%7}, {%8,%9}, {%0,%1,%2,%3};"
                 : "+f"(d[0]), "+f"(d[1]), "+f"(d[2]), "+f"(d[3])
                 : "r"(a[0]), "r"(a[1]), "r"(a[2]), "r"(a[3]), "r"(b[0]), "r"(b[1]));
}

// 2-way fp16 split of an fp32 pair -> two packed half2 words (hi image, residual image)
__device__ __forceinline__ void split2h(float a, float b, uint32_t& w0, uint32_t& w1) {
    __half a0 = __float2half_rn(a), b0 = __float2half_rn(b);
    __half a1 = __float2half_rn(a - __half2float(a0));
    __half b1 = __float2half_rn(b - __half2float(b0));
    w0 = ((uint32_t)__half_as_ushort(b0) << 16) | (uint32_t)__half_as_ushort(a0);
    w1 = ((uint32_t)__half_as_ushort(b1) << 16) | (uint32_t)__half_as_ushort(a1);
}

// 32-col tiles: 0-7 new_if(gc 320..575), 8-9 att(gc 256..319), 10-17 h1(gc 0..255), 18-25 w2
__device__ __host__ __forceinline__ int tile_gc(int tl) {
    return (tl < 8) ? 320 + tl * 32 : (tl < 10) ? 256 + (tl - 8) * 32
          : (tl < 18) ? (tl - 10) * 32 : (tl - 18) * 32;
}

// ---------------- K0: pack ----------------
__global__ void pack_kernel(const float* __restrict__ w1, const float* __restrict__ watt,
                            const float* __restrict__ wif, const float* __restrict__ b1,
                            const float* __restrict__ batt, const float* __restrict__ bif,
                            const float* __restrict__ w2) {
    int idx = blockIdx.x * blockDim.x + threadIdx.x;
    if (idx < 512 * 576) {
        int r = idx / 576, c = idx - r * 576;
        g_Wcat[idx] = (c < 256) ? w1[r * 256 + c]
                     : (c < 320) ? watt[r * 64 + (c - 256)]
                                 : wif[r * 256 + (c - 320)];
    }
    if (idx < 576)
        g_bcat[idx] = (idx < 256) ? b1[idx] : (idx < 320) ? batt[idx - 256] : bif[idx - 320];
    if (idx < 26 * 8192) {
        int tl = idx >> 13, rr = idx & 8191;
        int n = rr >> 8, k = rr & 255;   // n in 0..31, k in 0..255
        float w;
        if (tl < 18) {
            int c = tile_gc(tl) + n, r = 512 + k;
            w = (c < 256) ? w1[r * 256 + c]
               : (c < 320) ? watt[r * 64 + (c - 256)]
                           : wif[r * 256 + (c - 320)];
        } else {
            w = w2[k * 256 + (tl - 18) * 32 + n];
        }
        __half v0 = __float2half_rn(w);
        __half v1 = __float2half_rn(w - __half2float(v0));
        int byte = n * 512 + ((k * 2) ^ ((n & 7) << 4));   // 16B-chunk XOR swizzle
        size_t base = (size_t)tl * 16384 + (byte >> 1);
        g_Bt[base] = v0;
        g_Bt[base + 8192] = v1;
    }
}

// ---------------- K1: P = x @ Wcat(part) ----------------
__device__ __forceinline__ void micro_fma32(const float* __restrict__ ap,
                                            const float* __restrict__ bp, float acc[4][4]) {
#pragma unroll 8
    for (int k = 0; k < 32; k++) {
        const float* apk = ap + k * 65;
        const float* bpk = bp + k * 65;
        float a0 = apk[0], a1 = apk[1], a2 = apk[2], a3 = apk[3];
        float b0 = bpk[0], b1 = bpk[1], b2 = bpk[2], b3 = bpk[3];
        acc[0][0] += a0*b0; acc[0][1] += a0*b1; acc[0][2] += a0*b2; acc[0][3] += a0*b3;
        acc[1][0] += a1*b0; acc[1][1] += a1*b1; acc[1][2] += a1*b2; acc[1][3] += a1*b3;
        acc[2][0] += a2*b0; acc[2][1] += a2*b1; acc[2][2] += a2*b2; acc[2][3] += a2*b3;
        acc[3][0] += a3*b0; acc[3][1] += a3*b1; acc[3][2] += a3*b2; acc[3][3] += a3*b3;
    }
}
__global__ void __launch_bounds__(256) p_kernel(const float* __restrict__ x) {
    extern __shared__ float sm[];
    float* xs = sm;
    float* wsh = xs + 256 * 65;
    int nb = blockIdx.x, part = blockIdx.y, cg = blockIdx.z;
    int t = threadIdx.x, ty = t >> 4, tx = t & 15;
    {
        int row = t >> 2, k0 = (t & 3) * 64;
        const float* src = x + (size_t)(nb * 64 + row) * 256 + k0;
#pragma unroll
        for (int k = 0; k < 64; k += 4) {
            float4 v = *(const float4*)(src + k);
            xs[(k0+k)*65+row]=v.x; xs[(k0+k+1)*65+row]=v.y;
            xs[(k0+k+2)*65+row]=v.z; xs[(k0+k+3)*65+row]=v.w;
        }
    }
    __syncthreads();
    for (int cc = cg * 3; cc < cg * 3 + 3; cc++) {
        float acc[4][4] = {};
        for (int kp = 0; kp < 8; kp++) {
            {
                int k = t >> 3, cb = (t & 7) * 8;
                const float* src = g_Wcat + (size_t)(part*256 + kp*32 + k)*576 + cc*64 + cb;
                float4 v0 = *(const float4*)src, v1 = *(const float4*)(src + 4);
                float* d = wsh + k*65 + cb;
                d[0]=v0.x; d[1]=v0.y; d[2]=v0.z; d[3]=v0.w;
                d[4]=v1.x; d[5]=v1.y; d[6]=v1.z; d[7]=v1.w;
            }
            __syncthreads();
            micro_fma32(xs + kp*32*65 + ty*4, wsh + tx*4, acc);
            __syncthreads();
        }
#pragma unroll
        for (int ri = 0; ri < 4; ri++) {
            float4 v = make_float4(acc[ri][0], acc[ri][1], acc[ri][2], acc[ri][3]);
            *(float4*)(g_P + (size_t)part*NN*576 + (size_t)(nb*64 + ty*4 + ri)*576 + cc*64 + tx*4) = v;
        }
    }
}

// ---------------- K2: fused per-site kernel ----------------
// smem (bytes): [16..528) idxs; A imgs at 1024 / 33792 (32KB each);
// B dbl buf 66560 / 99328 (32768 each); tbuf 132096 [64][260] fp32; afb 198656 [64][66].
__global__ void __launch_bounds__(256) big_kernel(
    const float* __restrict__ IF, const int* __restrict__ ai, const int* __restrict__ aj,
    const float* __restrict__ g1, const float* __restrict__ be1,
    const float* __restrict__ gatt, const float* __restrict__ beatt,
    const float* __restrict__ gif, const float* __restrict__ beif,
    const float* __restrict__ b2, const float* __restrict__ g2, const float* __restrict__ be2,
    const float* __restrict__ wpre, const float* __restrict__ bpre,
    const int* __restrict__ mask,
    const float* __restrict__ wg, const float* __restrict__ bg,
    const float* __restrict__ gg, const float* __restrict__ beg,
    float* __restrict__ out) {
    extern __shared__ char smem[];
    const unsigned sb = (unsigned)__cvta_generic_to_shared(smem);
    int* idxs = (int*)(smem + 16);
    char* Agen = smem + 1024;
    const unsigned Abase = sb + 1024;
    const unsigned Bb[2] = { sb + 66560, sb + 99328 };
    float* tbuf = (float*)(smem + 132096);   // [64][260]
    float* afb  = (float*)(smem + 198656);   // [64][66]
    float* slog = (float*)(smem + 66560);    // aliases, used after GEMMs
    float* wsm  = (float*)(smem + 67584);
    float* aggs = (float*)(smem + 68608);
    float* red  = (float*)(smem + 69632);

    const int n = blockIdx.x, t = threadIdx.x;
    const int lane = t & 31, wid = t >> 5;
    const int mrow0 = (wid >> 1) << 4;       // M16 group (4 groups across warp pairs)
    const int nh16 = (wid & 1) << 4;         // N16 half within 32-col tile
    const float NEG = __int_as_float(0xff800000);
    const float inv256 = 1.f / 256.f, inv64 = 1.f / 64.f;

    // ldmatrix geometry: A fragment (m16k16)
    const int arow = mrow0 + (lane & 15);
    const unsigned abase_off = (unsigned)(arow * 512);
    const unsigned asw = (unsigned)((arow & 7) << 4);
    const unsigned achunk = (unsigned)((lane >> 4) << 4);
    // B fragment (n16k16)
    const int brow = nh16 + ((lane >> 4) << 3) + (lane & 7);
    const unsigned bbase_off = (unsigned)(brow * 512);
    const unsigned bsw = (unsigned)((brow & 7) << 4);
    const unsigned bchunk = (unsigned)(((lane >> 3) & 1) << 4);
    // epilogue geometry (lane-constant)
    const int eg = lane >> 2, etig = lane & 3;
    const int er0 = mrow0 + eg, er1 = mrow0 + eg + 8;

    if (t < 64) { idxs[t] = ai[n * 64 + t]; idxs[64 + t] = aj[n * 64 + t]; }

    // prefetch B tile 0 (2-term tile: hi image only, 16KB)
    {
        const char* src = (const char*)g_Bt;
#pragma unroll
        for (int i = 0; i < 4; i++) {
            unsigned off = (unsigned)(i * 4096 + t * 16);
            asm volatile("cp.async.cg.shared.global [%0], [%1], 16;" :: "r"(Bb[0] + off), "l"(src + off) : "memory");
        }
        CP_COMMIT();
    }

    // convert IF -> A (2 fp16 images, swizzled)
    {
        int row = t >> 2, k0 = (t & 3) * 64;
        const float* src = IF + (size_t)(n * 64 + row) * 256 + k0;
#pragma unroll
        for (int c = 0; c < 8; c++) {
            float4 v0 = *(const float4*)(src + c * 8);
            float4 v1 = *(const float4*)(src + c * 8 + 4);
            uint4 i0, i1;
            split2h(v0.x, v0.y, i0.x, i1.x);
            split2h(v0.z, v0.w, i0.y, i1.y);
            split2h(v1.x, v1.y, i0.z, i1.z);
            split2h(v1.z, v1.w, i0.w, i1.w);
            unsigned off = (unsigned)(row * 512 + (((k0 + c * 8) * 2) ^ ((row & 7) << 4)));
            *(uint4*)(Agen + off) = i0;
            *(uint4*)(Agen + 32768 + off) = i1;
        }
    }

    // ================= main tile loop (26 x 32-col tiles), ONE sync per tile =================
#pragma unroll 1
    for (int tl = 0; tl < 26; tl++) {
        CP_WAIT0();          // this thread's B[tl] chunks landed
        __syncthreads();     // all threads' B[tl] visible; all warps done with mma(tl-1)

        // issue prefetch of B[tl+1] into the buffer last used by tile tl-1 (safe after sync)
        if (tl < 25) {
            const char* src = (const char*)g_Bt + (size_t)(tl + 1) * 32768;
            unsigned dst = Bb[(tl + 1) & 1];
            int nch = (tl + 1 < 10) ? 4 : 8;   // 2-term tiles: hi image only
#pragma unroll 1
            for (int i = 0; i < nch; i++) {
                unsigned off = (unsigned)(i * 4096 + t * 16);
                asm volatile("cp.async.cg.shared.global [%0], [%1], 16;" :: "r"(dst + off), "l"(src + off) : "memory");
            }
            CP_COMMIT();
        }

        // ---- register-prefetch epilogue operands (hidden under mma loop) ----
        float2 p_pi0[2], p_pj0[2], p_pi1[2], p_pj1[2], p_bb[2];
        {
            int gc_e = tile_gc(tl);
            if (tl < 18) {
#pragma unroll
                for (int j = 0; j < 2; j++) {
                    int colg = gc_e + nh16 + j * 8 + 2 * etig;
                    p_bb[j]  = *(const float2*)(g_bcat + colg);
                    p_pi0[j] = *(const float2*)(g_P + (size_t)idxs[er0] * 576 + colg);
                    p_pj0[j] = *(const float2*)(g_P + (size_t)NN * 576 + (size_t)idxs[64 + er0] * 576 + colg);
                    p_pi1[j] = *(const float2*)(g_P + (size_t)idxs[er1] * 576 + colg);
                    p_pj1[j] = *(const float2*)(g_P + (size_t)NN * 576 + (size_t)idxs[64 + er1] * 576 + colg);
                }
            } else {
#pragma unroll
                for (int j = 0; j < 2; j++) {
                    int colg = gc_e + nh16 + j * 8 + 2 * etig;
                    p_bb[j]  = *(const float2*)(b2 + colg);
                    p_pi0[j] = p_pj0[j] = p_pi1[j] = p_pj1[j] = make_float2(0.f, 0.f);
                }
            }
        }

        // dd[j*3 + term][4] for n8 halves j=0,1; terms a0b0, a1b0, a0b1
        const bool full = (tl >= 10);   // selection chain: 3-term; new_if/att: 2-term
        float dd[6][4] = {};
        const unsigned Bt0 = Bb[tl & 1];
#pragma unroll 8
        for (int ks = 0; ks < 16; ks++) {
            unsigned kb = (unsigned)(ks << 5);
            unsigned aoff = abase_off + ((kb + achunk) ^ asw);
            unsigned boff = bbase_off + ((kb + bchunk) ^ bsw);
            unsigned a0[4], a1[4], b0[4];
            ldsm4(a0, Abase + aoff);
            ldsm4(a1, Abase + 32768 + aoff);
            ldsm4(b0, Bt0 + boff);
            mma16816h(dd[0], a0, b0);
            mma16816h(dd[1], a1, b0);
            mma16816h(dd[3], a0, b0 + 2);
            mma16816h(dd[4], a1, b0 + 2);
            if (full) {
                unsigned b1[4];
                ldsm4(b1, Bt0 + 16384 + boff);
                mma16816h(dd[2], a0, b1);
                mma16816h(dd[5], a0, b1 + 2);
            }
        }

        // ---- epilogue (uniform adds; p_* are zero for w2 tiles) ----
        {
            float* dst; int dstride, dcol;
            if (tl < 8)       { dst = tbuf; dstride = 260; dcol = tl * 32; }
            else if (tl < 10) { dst = afb;  dstride = 66;  dcol = (tl - 8) * 32; }
            else if (tl < 18) { dst = tbuf; dstride = 260; dcol = (tl - 10) * 32; }
            else              { dst = tbuf; dstride = 260; dcol = (tl - 18) * 32; }
#pragma unroll
            for (int j = 0; j < 2; j++) {
                float e0 = dd[j*3][0] + dd[j*3+1][0] + dd[j*3+2][0];
                float e1 = dd[j*3][1] + dd[j*3+1][1] + dd[j*3+2][1];
                float e2 = dd[j*3][2] + dd[j*3+1][2] + dd[j*3+2][2];
                float e3 = dd[j*3][3] + dd[j*3+1][3] + dd[j*3+2][3];
                int dc = dcol + nh16 + j * 8 + 2 * etig;
                *(float2*)(dst + (size_t)er0 * dstride + dc) =
                    make_float2(e0 + p_pi0[j].x + p_pj0[j].x + p_bb[j].x,
                                e1 + p_pi0[j].y + p_pj0[j].y + p_bb[j].y);
                *(float2*)(dst + (size_t)er1 * dstride + dc) =
                    make_float2(e2 + p_pi1[j].x + p_pj1[j].x + p_bb[j].x,
                                e3 + p_pi1[j].y + p_pj1[j].y + p_bb[j].y);
            }
        }

        // ---- segment boundaries (own syncs) ----
        if (tl == 7) {
            __syncthreads();
            // LN new_if -> out
#pragma unroll 1
            for (int rr = 0; rr < 8; rr++) {
                int row = rr * 8 + wid;
                const float* trow = tbuf + row * 260;
                float v[8], s = 0.f, qq = 0.f;
#pragma unroll
                for (int j = 0; j < 8; j++) {
                    float xv = fmaxf(trow[lane + j * 32], 0.f);
                    v[j] = xv; s += xv; qq += xv * xv;
                }
                s = warp_sum(s); qq = warp_sum(qq);
                float mu = s * inv256, rstd = rsqrtf(qq * inv256 - mu * mu + EPS);
                float* o = out + 524288 + ((size_t)n * 64 + row) * 256;
#pragma unroll
                for (int j = 0; j < 8; j++) {
                    int c = lane + j * 32;
                    o[c] = (v[j] - mu) * rstd * gif[c] + beif[c];
                }
            }
        }
        if (tl == 17) {
            __syncthreads();
            // LN att (afb in place) + LN h1 (tbuf in place)
#pragma unroll 1
            for (int rr = 0; rr < 8; rr++) {
                int row = rr * 8 + wid;
                {
                    float* ar = afb + row * 66;
                    float x0 = fmaxf(ar[lane], 0.f), x1 = fmaxf(ar[32 + lane], 0.f);
                    float s = warp_sum(x0 + x1), qq = warp_sum(x0 * x0 + x1 * x1);
                    float mu = s * inv64, rstd = rsqrtf(qq * inv64 - mu * mu + EPS);
                    ar[lane] = (x0 - mu) * rstd * gatt[lane] + beatt[lane];
                    ar[32 + lane] = (x1 - mu) * rstd * gatt[32 + lane] + beatt[32 + lane];
                }
                {
                    float* trow = tbuf + row * 260;
                    float v[8], s = 0.f, qq = 0.f;
#pragma unroll
                    for (int j = 0; j < 8; j++) {
                        float xv = fmaxf(trow[lane + j * 32], 0.f);
                        v[j] = xv; s += xv; qq += xv * xv;
                    }
                    s = warp_sum(s); qq = warp_sum(qq);
                    float mu = s * inv256, rstd = rsqrtf(qq * inv256 - mu * mu + EPS);
#pragma unroll
                    for (int j = 0; j < 8; j++) {
                        int c = lane + j * 32;
                        trow[c] = (v[j] - mu) * rstd * g1[c] + be1[c];
                    }
                }
            }
            __syncthreads();
            // rewrite A = h1 (2 fp16 images)
            {
                int row = t >> 2, k0 = (t & 3) * 64;
                const float* src = tbuf + row * 260 + k0;
#pragma unroll
                for (int c = 0; c < 8; c++) {
                    float4 v0 = *(const float4*)(src + c * 8);
                    float4 v1 = *(const float4*)(src + c * 8 + 4);
                    uint4 i0, i1;
                    split2h(v0.x, v0.y, i0.x, i1.x);
                    split2h(v0.z, v0.w, i0.y, i1.y);
                    split2h(v1.x, v1.y, i0.z, i1.z);
                    split2h(v1.z, v1.w, i0.w, i1.w);
                    unsigned off = (unsigned)(row * 512 + (((k0 + c * 8) * 2) ^ ((row & 7) << 4)));
                    *(uint4*)(Agen + off) = i0;
                    *(uint4*)(Agen + 32768 + off) = i1;
                }
            }
            __syncthreads();   // A rewrite visible before tile 18 mma
        }
    }
    __syncthreads();   // epilogue(25) writes visible for phase 4

    // ---- Phase 4: h2 = LN(relu(t2)); logits -> slog ----
#pragma unroll 1
    for (int rr = 0; rr < 8; rr++) {
        int row = rr * 8 + wid;
        const float* trow = tbuf + row * 260;
        float v[8], s = 0.f, qq = 0.f;
#pragma unroll
        for (int j = 0; j < 8; j++) {
            float xv = fmaxf(trow[lane + j * 32], 0.f);
            v[j] = xv; s += xv; qq += xv * xv;
        }
        s = warp_sum(s); qq = warp_sum(qq);
        float mu = s * inv256, rstd = rsqrtf(qq * inv256 - mu * mu + EPS);
        float l0 = 0.f, l1 = 0.f, l2 = 0.f, l3 = 0.f;
#pragma unroll
        for (int j = 0; j < 8; j++) {
            int c = lane + j * 32;
            float y = (v[j] - mu) * rstd * g2[c] + be2[c];
            float4 wp = *(const float4*)(wpre + (size_t)c * 4);
            l0 += y * wp.x; l1 += y * wp.y; l2 += y * wp.z; l3 += y * wp.w;
        }
        l0 = warp_sum(l0); l1 = warp_sum(l1); l2 = warp_sum(l2); l3 = warp_sum(l3);
        if (lane == 0) {
            bool mk = mask[n * 64 + row] != 0;
            slog[row * 4 + 0] = mk ? NEG : (l0 + bpre[0]);
            slog[row * 4 + 1] = mk ? NEG : (l1 + bpre[1]);
            slog[row * 4 + 2] = mk ? NEG : (l2 + bpre[2]);
            slog[row * 4 + 3] = mk ? NEG : (l3 + bpre[3]);
        }
    }
    __syncthreads();

    // ---- Phase 5: per-head top-16 softmax ----
    if (wid < 4) {
        int h = wid;
        float v0 = slog[lane * 4 + h], v1 = slog[(32 + lane) * 4 + h];
        float c0 = v0, c1 = v1;
        float thr = NEG, maxv = NEG;
#pragma unroll 1
        for (int it = 0; it < 16; it++) {
            float loc = fmaxf(c0, c1);
            float m = warp_max(loc);
            if (it == 0) maxv = m;
            if (m == NEG) break;
            thr = m;
            unsigned bl = __ballot_sync(0xffffffffu, loc == m);
            int src = __ffs(bl) - 1;
            if (lane == src) { if (c0 == m) c0 = NEG; else c1 = NEG; }
        }
        float e0 = (v0 >= thr) ? expf(v0 - maxv) : 0.f;
        float e1 = (v1 >= thr) ? expf(v1 - maxv) : 0.f;
        float inv = 1.f / warp_sum(e0 + e1);
        wsm[h * 64 + lane] = e0 * inv;
        wsm[h * 64 + 32 + lane] = e1 * inv;
    }
    __syncthreads();

    // ---- Phase 6: agg[d,h] = sum_m w[h,m] * af[m,d] ----
    {
        int d = t >> 2, h = t & 3;
        float s = 0.f;
#pragma unroll
        for (int m = 0; m < 64; m++) s += wsm[h * 64 + m] * afb[m * 66 + d];
        aggs[t] = s;
    }
    __syncthreads();

    // ---- Phase 7: x_out = LN(relu(agg @ wg + bg)) ----
    {
        float v0a = 0.f, v1a = 0.f, v2a = 0.f, v3a = 0.f;
        float v4a = 0.f, v5a = 0.f, v6a = 0.f, v7a = 0.f;
#pragma unroll 4
        for (int k = 0; k < 256; k += 8) {
            v0a += aggs[k]     * wg[(size_t)k * 256 + t];
            v1a += aggs[k + 1] * wg[(size_t)(k + 1) * 256 + t];
            v2a += aggs[k + 2] * wg[(size_t)(k + 2) * 256 + t];
            v3a += aggs[k + 3] * wg[(size_t)(k + 3) * 256 + t];
            v4a += aggs[k + 4] * wg[(size_t)(k + 4) * 256 + t];
            v5a += aggs[k + 5] * wg[(size_t)(k + 5) * 256 + t];
            v6a += aggs[k + 6] * wg[(size_t)(k + 6) * 256 + t];
            v7a += aggs[k + 7] * wg[(size_t)(k + 7) * 256 + t];
        }
        float v = fmaxf(((v0a + v1a) + (v2a + v3a)) + ((v4a + v5a) + (v6a + v7a)) + bg[t], 0.f);
        float s = warp_sum(v), qq = warp_sum(v * v);
        if (lane == 0) { red[wid] = s; red[8 + wid] = qq; }
        __syncthreads();
        if (t < 32) {
            float a = (lane < 8) ? red[lane] : 0.f;
            float b = (lane < 8) ? red[8 + lane] : 0.f;
#pragma unroll
            for (int o = 4; o; o >>= 1) {
                a += __shfl_xor_sync(0xffffffffu, a, o);
                b += __shfl_xor_sync(0xffffffffu, b, o);
            }
            if (lane == 0) { red[0] = a; red[8] = b; }
        }
        __syncthreads();
        float mu = red[0] * inv256, rstd = rsqrtf(red[8] * inv256 - mu * mu + EPS);
        float y = (v - mu) * rstd * gg[t] + beg[t];
        out[(size_t)n * 256 + t] = y;
        out[34078720ull + (size_t)n * 256 + t] = y;
    }
}

// ---------------- launch ----------------
extern "C" void kernel_launch(void* const* d_in, const int* in_sizes, int n_in,
                              void* d_out, int out_size) {
    const float* x = (const float*)d_in[0];
    const float* iff = (const float*)d_in[1];
    const int* mask = (const int*)d_in[2];
    const int* ai = (const int*)d_in[3];
    const int* aj = (const int*)d_in[4];
    const float* w1 = (const float*)d_in[5], *b1 = (const float*)d_in[6];
    const float* g1 = (const float*)d_in[7], *be1 = (const float*)d_in[8];
    const float* w2 = (const float*)d_in[9], *b2 = (const float*)d_in[10];
    const float* g2 = (const float*)d_in[11], *be2 = (const float*)d_in[12];
    const float* wpre = (const float*)d_in[13], *bpre = (const float*)d_in[14];
    const float* watt = (const float*)d_in[15], *batt = (const float*)d_in[16];
    const float* gatt = (const float*)d_in[17], *beatt = (const float*)d_in[18];
    const float* wif = (const float*)d_in[19], *bif = (const float*)d_in[20];
    const float* gif = (const float*)d_in[21], *beif = (const float*)d_in[22];
    const float* wg = (const float*)d_in[23], *bg = (const float*)d_in[24];
    const float* gg = (const float*)d_in[25], *beg = (const float*)d_in[26];
    float* out = (float*)d_out;

    const int PS = (256 * 65 + 32 * 65) * 4;
    const int BS = 215552;
    cudaFuncSetAttribute(p_kernel, cudaFuncAttributeMaxDynamicSharedMemorySize, PS);
    cudaFuncSetAttribute(big_kernel, cudaFuncAttributeMaxDynamicSharedMemorySize, BS);

    pack_kernel<<<1152, 256>>>(w1, watt, wif, b1, batt, bif, w2);
    p_kernel<<<dim3(32, 2, 3), 256, PS>>>(x);
    big_kernel<<<2048, 256, BS>>>(iff, ai, aj, g1, be1, gatt, beatt, gif, beif,
                                  b2, g2, be2, wpre, bpre, mask,
                                  wg, bg, gg, beg, out);
}